// round 7
// baseline (speedup 1.0000x reference)
#include <cuda_runtime.h>
#include <cuda_fp16.h>
#include <math.h>

#define Bdim 4
#define Ldim 1024
#define Hdim 16
#define Ddim 64
#define HIDdim 1024
#define BHdim (Bdim*Hdim)

// Scratch intermediates (allocation-free rule: __device__ globals)
__device__ float g_q[BHdim*Ldim*Ddim];
__device__ float g_k[BHdim*Ldim*Ddim];
__device__ float g_v[BHdim*Ldim*Ddim];   // stored TRANSPOSED: [BH][D][L]
__device__ float g_att[BHdim*Ldim*Ddim]; // [BH][L][D]

__device__ __forceinline__ unsigned f2h2(float lo, float hi) {
    __half2 h = __float22half2_rn(make_float2(lo, hi));
    return *(unsigned*)&h;
}
__device__ __forceinline__ unsigned pk2(const float2 v) { return f2h2(v.x, v.y); }

// m16n8k16 fp16 mma, fp32 accumulate.
__device__ __forceinline__ void mma_f16(
    float& c0, float& c1, float& c2, float& c3,
    unsigned a0, unsigned a1, unsigned a2, unsigned a3,
    unsigned b0, unsigned b1)
{
    asm volatile(
        "mma.sync.aligned.m16n8k16.row.col.f32.f16.f16.f32 "
        "{%0,%1,%2,%3}, {%4,%5,%6,%7}, {%8,%9}, {%0,%1,%2,%3};"
        : "+f"(c0), "+f"(c1), "+f"(c2), "+f"(c3)
        : "r"(a0), "r"(a1), "r"(a2), "r"(a3), "r"(b0), "r"(b1));
}

__device__ __forceinline__ void cp16(void* smem, const void* gmem) {
    unsigned sa = (unsigned)__cvta_generic_to_shared(smem);
    asm volatile("cp.async.cg.shared.global [%0], [%1], 16;" :: "r"(sa), "l"(gmem));
}
#define CP_COMMIT() asm volatile("cp.async.commit_group;")
#define CP_WAIT0()  asm volatile("cp.async.wait_group 0;")
#define CP_WAIT1()  asm volatile("cp.async.wait_group 1;")

#define GEMM_SMEM (2 * 2 * 128 * 36 * 4)

// ---------------------------------------------------------------------------
// GEMM core (cp.async double-buffered k-pipeline), fp16 mma fp32 accum.
// 128x128 tile of A[M0..] @ W[N0..]^T, both row-major K=1024.
// 8 warps 2m x 4n, warp tile 64x32, k-steps of 16 (2 per 32-k stage).
// smem staged fp32 (cp.async can't convert); cvt to half2 at fragment read.
// ---------------------------------------------------------------------------
struct GemmCore {
    float c[4][4][4];

    template<class SrcA>
    __device__ __forceinline__ void run(
        float* smf, SrcA srcA, const float* __restrict__ W,
        int M0, int N0, int tid, int wm, int wn, int grp, int tig)
    {
        float* As = smf;
        float* Ws = smf + 2 * 128 * 36;
        #pragma unroll
        for (int mi = 0; mi < 4; mi++)
            #pragma unroll
            for (int ni = 0; ni < 4; ni++)
                #pragma unroll
                for (int r = 0; r < 4; r++) c[mi][ni][r] = 0.f;

        auto issue = [&](int kt, int s) {
            const int k0 = kt * 32;
            #pragma unroll
            for (int p = 0; p < 4; p++) {
                const int cid = tid + p * 256;
                const int m = cid >> 3;
                const int cc = (cid & 7) << 2;
                cp16(&As[((size_t)s * 128 + m) * 36 + cc], srcA(M0 + m, k0 + cc));
                cp16(&Ws[((size_t)s * 128 + m) * 36 + cc],
                     W + (size_t)(N0 + m) * 1024 + k0 + cc);
            }
            CP_COMMIT();
        };

        issue(0, 0);
        for (int kt = 0; kt < 32; kt++) {
            const int s = kt & 1;
            if (kt + 1 < 32) { issue(kt + 1, s ^ 1); CP_WAIT1(); }
            else             { CP_WAIT0(); }
            __syncthreads();

            const float* as = As + (size_t)s * 128 * 36;
            const float* ws = Ws + (size_t)s * 128 * 36;
            #pragma unroll
            for (int ks = 0; ks < 2; ks++) {
                const int kk = ks * 16 + tig * 2;
                unsigned af[4][4], bf[4][2];
                #pragma unroll
                for (int mi = 0; mi < 4; mi++) {
                    const int r = wm * 64 + mi * 16 + grp;
                    af[mi][0] = pk2(*(const float2*)&as[r * 36 + kk]);
                    af[mi][1] = pk2(*(const float2*)&as[(r + 8) * 36 + kk]);
                    af[mi][2] = pk2(*(const float2*)&as[r * 36 + kk + 8]);
                    af[mi][3] = pk2(*(const float2*)&as[(r + 8) * 36 + kk + 8]);
                }
                #pragma unroll
                for (int ni = 0; ni < 4; ni++) {
                    const int n = wn * 32 + ni * 8 + grp;
                    bf[ni][0] = pk2(*(const float2*)&ws[n * 36 + kk]);
                    bf[ni][1] = pk2(*(const float2*)&ws[n * 36 + kk + 8]);
                }
                #pragma unroll
                for (int mi = 0; mi < 4; mi++)
                    #pragma unroll
                    for (int ni = 0; ni < 4; ni++)
                        mma_f16(c[mi][ni][0], c[mi][ni][1], c[mi][ni][2], c[mi][ni][3],
                                af[mi][0], af[mi][1], af[mi][2], af[mi][3],
                                bf[ni][0], bf[ni][1]);
            }
            __syncthreads();
        }
    }
};

// ---------------------------------------------------------------------------
// Merged Q/K/V projection: 768 blocks, z = blockIdx.x>>8 selects which GEMM.
//   z=0: g_q = queries @ Wq^T + bq (split-head); z=1: g_k likewise;
//   z=2: g_v^T = Wv @ values^T + bv (transposed store, bias by ROW)
// ---------------------------------------------------------------------------
__global__ void __launch_bounds__(256) qkv_gemm(
    const float* __restrict__ queries, const float* __restrict__ keys,
    const float* __restrict__ values,
    const float* __restrict__ Wq_w, const float* __restrict__ Wq_b,
    const float* __restrict__ Wk_w, const float* __restrict__ Wk_b,
    const float* __restrict__ Wv_w, const float* __restrict__ Wv_b)
{
    extern __shared__ float smf[];
    const int g = blockIdx.x;
    const int z = g >> 8;
    const int r = g & 255;
    const int tid = threadIdx.x;
    const int wid = tid >> 5;
    const int lane = tid & 31;
    const int grp = lane >> 2;
    const int tig = lane & 3;
    const int wm = wid >> 2;
    const int wn = wid & 3;

    const float *A, *W, *bias;
    int M0, N0;
    if (z == 0)      { A = queries; W = Wq_w; bias = Wq_b; M0 = (r >> 3) * 128; N0 = (r & 7) * 128; }
    else if (z == 1) { A = keys;    W = Wk_w; bias = Wk_b; M0 = (r >> 3) * 128; N0 = (r & 7) * 128; }
    else             { A = Wv_w;    W = values; bias = Wv_b; M0 = (r & 7) * 128; N0 = (r >> 3) * 128; }

    GemmCore gc;
    gc.run(smf, [&](int m, int k) { return A + (size_t)m * 1024 + k; },
           W, M0, N0, tid, wm, wn, grp, tig);

    #pragma unroll
    for (int mi = 0; mi < 4; mi++) {
        #pragma unroll
        for (int ni = 0; ni < 4; ni++) {
            const int r0 = M0 + wm * 64 + mi * 16 + grp;
            const int r1 = r0 + 8;
            const int cn = N0 + wn * 32 + ni * 8 + tig * 2;
            if (z == 2) {
                const float bv0 = bias[r0], bv1 = bias[r1];
                float2 v0 = make_float2(gc.c[mi][ni][0] + bv0, gc.c[mi][ni][1] + bv0);
                float2 v1 = make_float2(gc.c[mi][ni][2] + bv1, gc.c[mi][ni][3] + bv1);
                const size_t base = (size_t)(cn >> 10) * 1048576 + (cn & 1023);
                *(float2*)(g_v + base + (size_t)r0 * 1024) = v0;
                *(float2*)(g_v + base + (size_t)r1 * 1024) = v1;
            } else {
                float* dst = (z == 0) ? g_q : g_k;
                const float bv0 = bias[cn], bv1 = bias[cn + 1];
                float2 v0 = make_float2(gc.c[mi][ni][0] + bv0, gc.c[mi][ni][1] + bv1);
                float2 v1 = make_float2(gc.c[mi][ni][2] + bv0, gc.c[mi][ni][3] + bv1);
                const int h = cn >> 6, d = cn & 63;
                const int bi0 = r0 >> 10, l0 = r0 & 1023;
                const int bi1 = r1 >> 10, l1 = r1 & 1023;
                *(float2*)(dst + (((size_t)(bi0 * Hdim + h)) * Ldim + l0) * Ddim + d) = v0;
                *(float2*)(dst + (((size_t)(bi1 * Hdim + h)) * Ldim + l1) * Ddim + d) = v1;
            }
        }
    }
}

// ---------------------------------------------------------------------------
// Output projection: out = merge_heads(g_att) @ Wo^T + bo
// ---------------------------------------------------------------------------
__global__ void __launch_bounds__(256) out_gemm(
    const float* __restrict__ W,
    const float* __restrict__ bias,
    float* __restrict__ Cout)
{
    extern __shared__ float smf[];
    const int M0 = blockIdx.y * 128;
    const int N0 = blockIdx.x * 128;
    const int tid = threadIdx.x;
    const int wid = tid >> 5;
    const int lane = tid & 31;
    const int grp = lane >> 2;
    const int tig = lane & 3;
    const int wm = wid >> 2;
    const int wn = wid & 3;

    GemmCore gc;
    gc.run(smf,
        [&](int m, int k) {
            const int bi = m >> 10, l = m & 1023;
            const int h = k >> 6, d = k & 63;
            return (const float*)(g_att + (((size_t)(bi * Hdim + h)) * Ldim + l) * Ddim + d);
        },
        W, M0, N0, tid, wm, wn, grp, tig);

    #pragma unroll
    for (int mi = 0; mi < 4; mi++) {
        #pragma unroll
        for (int ni = 0; ni < 4; ni++) {
            const int r0 = M0 + wm * 64 + mi * 16 + grp;
            const int r1 = r0 + 8;
            const int cn = N0 + wn * 32 + ni * 8 + tig * 2;
            const float bv0 = bias[cn], bv1 = bias[cn + 1];
            *(float2*)(Cout + (size_t)r0 * 1024 + cn) =
                make_float2(gc.c[mi][ni][0] + bv0, gc.c[mi][ni][1] + bv1);
            *(float2*)(Cout + (size_t)r1 * 1024 + cn) =
                make_float2(gc.c[mi][ni][2] + bv0, gc.c[mi][ni][3] + bv1);
        }
    }
}

// ---------------------------------------------------------------------------
// Fused flash attention, fp16 mma + cp.async pipelined.
// Per 64-key tile t:
//   wait K[t] -> S=Q@K^T -> sync -> issue K[t+1]
//   wait {V,prev}[t] -> blend prev (write scores) -> mask -> online softmax
//   -> P (half2) -> sync -> O += P@V -> sync -> issue {V,prev}[t+1]
// smem: uQ half2[128][36], fK fp32[64][68], fV fp32[64][68],
//       fP fp32[128][68] (prev) overlaid with uP half2[128][36] region.
// NOTE: prev staging needs fp32 [128][68]; P needs half2 [128][36]. We keep
// the fp32 extent and store P pairs into the first 36 unsigneds of each row.
// ---------------------------------------------------------------------------
#define SMEM_FUSED ((128*36 + 64*68 + 64*68 + 128*68) * 4)

__global__ void __launch_bounds__(256, 2) fused_attn(
    const float* __restrict__ prev,
    const int* __restrict__ mask,
    const float* __restrict__ gat,
    float* __restrict__ scores)
{
    extern __shared__ unsigned sm[];
    unsigned* uQ = sm;                        // [128][36] half2 pairs
    float* fK = (float*)(uQ + 128 * 36);      // [64][68] K tile [j][d] fp32
    float* fV = fK + 64 * 68;                 // [64][68] V^T tile [d][j] fp32
    float* fP = fV + 64 * 68;                 // [128][68] prev fp32
    unsigned* uP = (unsigned*)fP;             // [128][36] P half2 (row stride 68!)

    const int bh = blockIdx.y;
    const int q0 = blockIdx.x * 128;
    const int tid = threadIdx.x;
    const int w = tid >> 5;
    const int lane = tid & 31;
    const int grp = lane >> 2;
    const int tig = lane & 3;
    const int rw0 = w * 16 + grp;
    const int rw1 = rw0 + 8;
    const int gq0 = q0 + rw0;
    const int gq1 = q0 + rw1;

    const float* qg = g_q + (size_t)bh * Ldim * Ddim;
    const float* kg = g_k + (size_t)bh * Ldim * Ddim;
    const float* vg = g_v + (size_t)bh * Ddim * Ldim;   // transposed [d][l]
    const size_t sb = ((size_t)bh << 20);
    const float* prevb = prev + sb + (size_t)(q0 + w * 16) * Ldim;

    auto issueK = [&](int kt) {
        #pragma unroll
        for (int p = 0; p < 4; p++) {
            const int idx = tid + p * 256;
            const int r = idx >> 4;
            const int cc = (idx & 15) << 2;
            cp16(&fK[r * 68 + cc], kg + (size_t)(kt + r) * Ddim + cc);
        }
        CP_COMMIT();
    };
    auto issueVP = [&](int kt) {
        #pragma unroll
        for (int p = 0; p < 4; p++) {
            const int idx = tid + p * 256;
            const int r = idx >> 4;
            const int cc = (idx & 15) << 2;
            cp16(&fV[r * 68 + cc], vg + (size_t)r * Ldim + kt + cc);
        }
        #pragma unroll
        for (int j = 0; j < 8; j++) {
            const int cid = j * 32 + lane;
            const int r = cid >> 4;
            const int c4 = (cid & 15) << 2;
            cp16(&fP[(w * 16 + r) * 68 + c4], prevb + (size_t)r * Ldim + kt + c4);
        }
        CP_COMMIT();
    };

    issueK(0);
    issueVP(0);

    // Load Q tile once (128 x 64 fp32 -> half2 pairs)
    #pragma unroll
    for (int p = 0; p < 8; p++) {
        const int idx = tid + p * 256;
        const int m = idx >> 4;
        const int pc = (idx & 15) << 1;   // pair index 0..30
        const float4 va = *(const float4*)(qg + (size_t)(q0 + m) * Ddim + (pc << 1));
        uQ[m * 36 + pc]     = f2h2(va.x, va.y);
        uQ[m * 36 + pc + 1] = f2h2(va.z, va.w);
    }

    const int vl0 = mask[(bh & 3) * Ldim + gq0];
    const int vl1 = mask[(bh & 3) * Ldim + gq1];
    const float gv = 1.f / (1.f + __expf(-gat[0]));
    const float og = 1.f - gv;

    float o[8][4];
    #pragma unroll
    for (int ni = 0; ni < 8; ni++)
        #pragma unroll
        for (int r = 0; r < 4; r++) o[ni][r] = 0.f;
    float mi0 = -1e30f, mi1 = -1e30f, li0 = 0.f, li1 = 0.f;

    for (int kt = 0; kt < Ldim; kt += 64) {
        const bool more = (kt + 64 < Ldim);

        CP_WAIT1();          // K[t] ready ({V,prev}[t] may be pending)
        __syncthreads();

        // S = Q @ K^T : 4 k-steps of 16
        float cs[8][4];
        #pragma unroll
        for (int ni = 0; ni < 8; ni++)
            #pragma unroll
            for (int r = 0; r < 4; r++) cs[ni][r] = 0.f;

        #pragma unroll
        for (int ks = 0; ks < 4; ks++) {
            const unsigned a0 = uQ[rw0 * 36 + ks * 8 + tig];
            const unsigned a1 = uQ[rw1 * 36 + ks * 8 + tig];
            const unsigned a2 = uQ[rw0 * 36 + ks * 8 + tig + 4];
            const unsigned a3 = uQ[rw1 * 36 + ks * 8 + tig + 4];
            const int kc = ks * 16 + tig * 2;
            #pragma unroll
            for (int ni = 0; ni < 8; ni++) {
                const unsigned b0 = pk2(*(const float2*)&fK[(ni * 8 + grp) * 68 + kc]);
                const unsigned b1 = pk2(*(const float2*)&fK[(ni * 8 + grp) * 68 + kc + 8]);
                mma_f16(cs[ni][0], cs[ni][1], cs[ni][2], cs[ni][3],
                        a0, a1, a2, a3, b0, b1);
            }
        }
        __syncthreads();               // K buffer free
        if (more) issueK(kt + 64);

        if (more) CP_WAIT1(); else CP_WAIT0();   // {V,prev}[t] ready
        __syncwarp();                  // prev rows are warp-local

        // blend with prev, write scores, mask+scale
        float m0 = -1e30f, m1 = -1e30f;
        #pragma unroll
        for (int ni = 0; ni < 8; ni++) {
            const int cl = ni * 8 + tig * 2;
            const int col = kt + cl;
            const float2 p0 = *(const float2*)&fP[rw0 * 68 + cl];
            const float2 p1 = *(const float2*)&fP[rw1 * 68 + cl];
            const float b00 = p0.x * gv + og * cs[ni][0];
            const float b01 = p0.y * gv + og * cs[ni][1];
            const float b10 = p1.x * gv + og * cs[ni][2];
            const float b11 = p1.y * gv + og * cs[ni][3];
            const size_t i0 = sb + (size_t)gq0 * Ldim + col;
            const size_t i1 = sb + (size_t)gq1 * Ldim + col;
            *(float2*)(scores + i0) = make_float2(b00, b01);
            *(float2*)(scores + i1) = make_float2(b10, b11);
            cs[ni][0] = (col     < vl0) ? b00 * 0.125f : -1e30f;
            cs[ni][1] = (col + 1 < vl0) ? b01 * 0.125f : -1e30f;
            cs[ni][2] = (col     < vl1) ? b10 * 0.125f : -1e30f;
            cs[ni][3] = (col + 1 < vl1) ? b11 * 0.125f : -1e30f;
            m0 = fmaxf(m0, fmaxf(cs[ni][0], cs[ni][1]));
            m1 = fmaxf(m1, fmaxf(cs[ni][2], cs[ni][3]));
        }
        m0 = fmaxf(m0, __shfl_xor_sync(0xffffffffu, m0, 1));
        m0 = fmaxf(m0, __shfl_xor_sync(0xffffffffu, m0, 2));
        m1 = fmaxf(m1, __shfl_xor_sync(0xffffffffu, m1, 1));
        m1 = fmaxf(m1, __shfl_xor_sync(0xffffffffu, m1, 2));

        const float mn0 = fmaxf(mi0, m0);
        const float mn1 = fmaxf(mi1, m1);
        const float cr0 = __expf(mi0 - mn0);
        const float cr1 = __expf(mi1 - mn1);
        li0 *= cr0; li1 *= cr1;
        #pragma unroll
        for (int ni = 0; ni < 8; ni++) {
            o[ni][0] *= cr0; o[ni][1] *= cr0;
            o[ni][2] *= cr1; o[ni][3] *= cr1;
        }
        mi0 = mn0; mi1 = mn1;

        // P = exp(s - m) -> half2 pairs into uP (row stride 68 unsigneds,
        // first 36 used; overlays prev rows this warp owns -> warp-local)
        #pragma unroll
        for (int ni = 0; ni < 8; ni++) {
            const float p00 = __expf(cs[ni][0] - mn0);
            const float p01 = __expf(cs[ni][1] - mn0);
            const float p10 = __expf(cs[ni][2] - mn1);
            const float p11 = __expf(cs[ni][3] - mn1);
            li0 += p00 + p01;
            li1 += p10 + p11;
            const int pc = ni * 4 + tig;
            uP[rw0 * 68 + pc] = f2h2(p00, p01);
            uP[rw1 * 68 + pc] = f2h2(p10, p11);
        }
        __syncwarp();

        // O += P @ V : 4 k-steps of 16
        #pragma unroll
        for (int ks = 0; ks < 4; ks++) {
            const unsigned a0 = uP[rw0 * 68 + ks * 8 + tig];
            const unsigned a1 = uP[rw1 * 68 + ks * 8 + tig];
            const unsigned a2 = uP[rw0 * 68 + ks * 8 + tig + 4];
            const unsigned a3 = uP[rw1 * 68 + ks * 8 + tig + 4];
            const int kc = ks * 16 + tig * 2;
            #pragma unroll
            for (int ni = 0; ni < 8; ni++) {
                const unsigned b0 = pk2(*(const float2*)&fV[(ni * 8 + grp) * 68 + kc]);
                const unsigned b1 = pk2(*(const float2*)&fV[(ni * 8 + grp) * 68 + kc + 8]);
                mma_f16(o[ni][0], o[ni][1], o[ni][2], o[ni][3],
                        a0, a1, a2, a3, b0, b1);
            }
        }
        __syncthreads();               // V + uP buffers free
        if (more) issueVP(kt + 64);
    }

    li0 += __shfl_xor_sync(0xffffffffu, li0, 1);
    li0 += __shfl_xor_sync(0xffffffffu, li0, 2);
    li1 += __shfl_xor_sync(0xffffffffu, li1, 1);
    li1 += __shfl_xor_sync(0xffffffffu, li1, 2);
    const float inv0 = 1.f / li0;
    const float inv1 = 1.f / li1;

    float* ab = g_att + (size_t)bh * Ldim * Ddim;
    #pragma unroll
    for (int ni = 0; ni < 8; ni++) {
        const int d = ni * 8 + tig * 2;
        *(float2*)(ab + (size_t)gq0 * Ddim + d) =
            make_float2(o[ni][0] * inv0, o[ni][1] * inv0);
        *(float2*)(ab + (size_t)gq1 * Ddim + d) =
            make_float2(o[ni][2] * inv1, o[ni][3] * inv1);
    }
}

// ---------------------------------------------------------------------------
// Launch.  Inputs: queries, keys, values, prev, mask(int32),
//   Wq_w, Wq_b, Wk_w, Wk_b, Wv_w, Wv_b, Wo_w, Wo_b, gat
// Output: [out (4M floats) | scores (64M floats)]
// ---------------------------------------------------------------------------
extern "C" void kernel_launch(void* const* d_in, const int* in_sizes, int n_in,
                              void* d_out, int out_size)
{
    (void)in_sizes; (void)n_in; (void)out_size;
    const float* queries = (const float*)d_in[0];
    const float* keys    = (const float*)d_in[1];
    const float* values  = (const float*)d_in[2];
    const float* prev    = (const float*)d_in[3];
    const int*   mask    = (const int*)d_in[4];
    const float* Wq_w = (const float*)d_in[5];
    const float* Wq_b = (const float*)d_in[6];
    const float* Wk_w = (const float*)d_in[7];
    const float* Wk_b = (const float*)d_in[8];
    const float* Wv_w = (const float*)d_in[9];
    const float* Wv_b = (const float*)d_in[10];
    const float* Wo_w = (const float*)d_in[11];
    const float* Wo_b = (const float*)d_in[12];
    const float* gat  = (const float*)d_in[13];

    float* out    = (float*)d_out;
    float* scores = out + (size_t)Bdim * Ldim * HIDdim;

    cudaFuncSetAttribute(fused_attn,
                         cudaFuncAttributeMaxDynamicSharedMemorySize, SMEM_FUSED);
    cudaFuncSetAttribute(qkv_gemm,
                         cudaFuncAttributeMaxDynamicSharedMemorySize, GEMM_SMEM);
    cudaFuncSetAttribute(out_gemm,
                         cudaFuncAttributeMaxDynamicSharedMemorySize, GEMM_SMEM);

    qkv_gemm<<<768, 256, GEMM_SMEM>>>(queries, keys, values,
                                      Wq_w, Wq_b, Wk_w, Wk_b, Wv_w, Wv_b);

    dim3 gf(8, 64);
    fused_attn<<<gf, 256, SMEM_FUSED>>>(prev, mask, gat, scores);

    dim3 gproj(8, 32);
    out_gemm<<<gproj, 256, GEMM_SMEM>>>(Wo_w, Wo_b, out);
}

// round 8
// speedup vs baseline: 1.8926x; 1.8926x over previous
#include <cuda_runtime.h>
#include <cuda_fp16.h>
#include <math.h>

#define Bdim 4
#define Ldim 1024
#define Hdim 16
#define Ddim 64
#define HIDdim 1024
#define BHdim (Bdim*Hdim)

// fp16 copies of GEMM operands (converted once at start)
__device__ __half h_qry[4194304];
__device__ __half h_key[4194304];
__device__ __half h_val[4194304];
__device__ __half h_wq[1048576];
__device__ __half h_wk[1048576];
__device__ __half h_wv[1048576];
__device__ __half h_wo[1048576];
// fp16 intermediates
__device__ __half g_qh[4194304];   // [BH][L][D]
__device__ __half g_kh[4194304];   // [BH][L][D]
__device__ __half g_vh[4194304];   // TRANSPOSED [BH][D][L]
__device__ __half g_atth[4194304]; // [BH][L][D]

__device__ __forceinline__ unsigned f2h2(float lo, float hi) {
    __half2 h = __float22half2_rn(make_float2(lo, hi));
    return *(unsigned*)&h;
}

__device__ __forceinline__ void mma_f16(
    float& c0, float& c1, float& c2, float& c3,
    unsigned a0, unsigned a1, unsigned a2, unsigned a3,
    unsigned b0, unsigned b1)
{
    asm volatile(
        "mma.sync.aligned.m16n8k16.row.col.f32.f16.f16.f32 "
        "{%0,%1,%2,%3}, {%4,%5,%6,%7}, {%8,%9}, {%0,%1,%2,%3};"
        : "+f"(c0), "+f"(c1), "+f"(c2), "+f"(c3)
        : "r"(a0), "r"(a1), "r"(a2), "r"(a3), "r"(b0), "r"(b1));
}

__device__ __forceinline__ void ldsm4(
    unsigned& r0, unsigned& r1, unsigned& r2, unsigned& r3, unsigned addr)
{
    asm volatile("ldmatrix.sync.aligned.m8n8.x4.shared.b16 {%0,%1,%2,%3}, [%4];"
        : "=r"(r0), "=r"(r1), "=r"(r2), "=r"(r3) : "r"(addr));
}

__device__ __forceinline__ void cp16(void* smem, const void* gmem) {
    unsigned sa = (unsigned)__cvta_generic_to_shared(smem);
    asm volatile("cp.async.cg.shared.global [%0], [%1], 16;" :: "r"(sa), "l"(gmem));
}
#define CP_COMMIT() asm volatile("cp.async.commit_group;")
#define CP_WAIT0()  asm volatile("cp.async.wait_group 0;")
#define CP_WAIT1()  asm volatile("cp.async.wait_group 1;")

// ---------------------------------------------------------------------------
// fp32 -> fp16 conversion of all GEMM operands. 16M floats, float4/thread.
// Layout: [qry 4M | key 4M | val 4M | wq 1M | wk 1M | wv 1M | wo 1M]
// ---------------------------------------------------------------------------
__global__ void __launch_bounds__(256) conv_half(
    const float* __restrict__ q, const float* __restrict__ k,
    const float* __restrict__ v,
    const float* __restrict__ wq, const float* __restrict__ wk,
    const float* __restrict__ wv, const float* __restrict__ wo)
{
    const size_t idx = (size_t)blockIdx.x * 256 + threadIdx.x;  // float4 unit
    const size_t e = idx * 4;
    const float* src;
    __half* dst;
    size_t off;
    if (e < 4194304)        { src = q;  dst = h_qry; off = e; }
    else if (e < 8388608)   { src = k;  dst = h_key; off = e - 4194304; }
    else if (e < 12582912)  { src = v;  dst = h_val; off = e - 8388608; }
    else {
        const size_t e2 = e - 12582912;
        const int s = (int)(e2 >> 20);
        off = e2 & 1048575;
        src = (s == 0) ? wq : (s == 1) ? wk : (s == 2) ? wv : wo;
        dst = (s == 0) ? h_wq : (s == 1) ? h_wk : (s == 2) ? h_wv : h_wo;
    }
    const float4 f = *(const float4*)(src + off);
    *(__half2*)(dst + off)     = __float22half2_rn(make_float2(f.x, f.y));
    *(__half2*)(dst + off + 2) = __float22half2_rn(make_float2(f.z, f.w));
}

// ---------------------------------------------------------------------------
// fp16 GEMM core: C[128,128] = A @ W^T (fp32 accum), K=1024, k-tile 64 halves,
// 16-stage cp.async double buffer, ldmatrix fragment feeds.
// 8 warps (2m x 4n), warp tile 64x32. smem rows: 72 halves (144B, conflict-free).
// ---------------------------------------------------------------------------
#define GEMM_SMEM (2 * 2 * 128 * 72 * 2)   // 73728 B

struct GemmCoreH {
    float c[4][4][4];

    template<class SrcA>
    __device__ __forceinline__ void run(
        __half* smh, SrcA srcA, const __half* __restrict__ W,
        int M0, int N0, int tid, int wm, int wn, int lane)
    {
        __half* As = smh;                  // [2][128][72]
        __half* Ws = smh + 2 * 128 * 72;   // [2][128][72]
        const unsigned uAs = (unsigned)__cvta_generic_to_shared(As);
        const unsigned uWs = (unsigned)__cvta_generic_to_shared(Ws);
        const int quad = lane >> 3, r8 = lane & 7;
        const int aoff = (((quad & 1) << 3) + r8) * 72 + ((quad >> 1) << 3);
        const int boff = (((quad >> 1) << 3) + r8) * 72 + ((quad & 1) << 3);

        #pragma unroll
        for (int mi = 0; mi < 4; mi++)
            #pragma unroll
            for (int ni = 0; ni < 4; ni++)
                #pragma unroll
                for (int r = 0; r < 4; r++) c[mi][ni][r] = 0.f;

        auto issue = [&](int kt, int s) {
            const int k0 = kt * 64;
            #pragma unroll
            for (int p = 0; p < 4; p++) {
                const int cid = tid + p * 256;
                const int m = cid >> 3;
                const int cc = (cid & 7) << 3;
                cp16(&As[(size_t)(s * 128 + m) * 72 + cc], srcA(M0 + m, k0 + cc));
                cp16(&Ws[(size_t)(s * 128 + m) * 72 + cc],
                     W + (size_t)(N0 + m) * 1024 + k0 + cc);
            }
            CP_COMMIT();
        };

        issue(0, 0);
        for (int kt = 0; kt < 16; kt++) {
            const int s = kt & 1;
            if (kt + 1 < 16) { issue(kt + 1, s ^ 1); CP_WAIT1(); }
            else             { CP_WAIT0(); }
            __syncthreads();

            const unsigned aBase = uAs + (unsigned)((s * 128 + wm * 64) * 72 + aoff) * 2;
            const unsigned bBase = uWs + (unsigned)((s * 128 + wn * 32) * 72 + boff) * 2;
            #pragma unroll
            for (int ks = 0; ks < 4; ks++) {
                const int kk = ks * 16;
                unsigned af[4][4], bf[4][2];
                #pragma unroll
                for (int mi = 0; mi < 4; mi++)
                    ldsm4(af[mi][0], af[mi][1], af[mi][2], af[mi][3],
                          aBase + (unsigned)(mi * 16 * 72 + kk) * 2);
                #pragma unroll
                for (int np = 0; np < 2; np++)
                    ldsm4(bf[2*np][0], bf[2*np][1], bf[2*np+1][0], bf[2*np+1][1],
                          bBase + (unsigned)(np * 16 * 72 + kk) * 2);
                #pragma unroll
                for (int mi = 0; mi < 4; mi++)
                    #pragma unroll
                    for (int ni = 0; ni < 4; ni++)
                        mma_f16(c[mi][ni][0], c[mi][ni][1], c[mi][ni][2], c[mi][ni][3],
                                af[mi][0], af[mi][1], af[mi][2], af[mi][3],
                                bf[ni][0], bf[ni][1]);
            }
            __syncthreads();
        }
    }
};

// ---------------------------------------------------------------------------
// Merged Q/K/V projection: 768 blocks, z = blockIdx.x>>8.
//   z=0: g_qh = qry @ Wq^T + bq (split-head, fp16 out)
//   z=1: g_kh likewise
//   z=2: g_vh^T = Wv @ val^T + bv (transposed fp16 out, bias by ROW)
// ---------------------------------------------------------------------------
__global__ void __launch_bounds__(256) qkv_gemm(
    const float* __restrict__ Wq_b, const float* __restrict__ Wk_b,
    const float* __restrict__ Wv_b)
{
    extern __shared__ __half smh[];
    const int g = blockIdx.x;
    const int z = g >> 8;
    const int r = g & 255;
    const int tid = threadIdx.x;
    const int wid = tid >> 5;
    const int lane = tid & 31;
    const int grp = lane >> 2;
    const int tig = lane & 3;
    const int wm = wid >> 2;
    const int wn = wid & 3;

    const __half *A, *W;
    const float* bias;
    int M0, N0;
    if (z == 0)      { A = h_qry; W = h_wq; bias = Wq_b; M0 = (r >> 3) * 128; N0 = (r & 7) * 128; }
    else if (z == 1) { A = h_key; W = h_wk; bias = Wk_b; M0 = (r >> 3) * 128; N0 = (r & 7) * 128; }
    else             { A = h_wv;  W = h_val; bias = Wv_b; M0 = (r & 7) * 128; N0 = (r >> 3) * 128; }

    GemmCoreH gc;
    gc.run(smh, [&](int m, int k) { return (const void*)(A + (size_t)m * 1024 + k); },
           W, M0, N0, tid, wm, wn, lane);

    #pragma unroll
    for (int mi = 0; mi < 4; mi++) {
        #pragma unroll
        for (int ni = 0; ni < 4; ni++) {
            const int r0 = M0 + wm * 64 + mi * 16 + grp;
            const int r1 = r0 + 8;
            const int cn = N0 + wn * 32 + ni * 8 + tig * 2;
            if (z == 2) {
                const float bv0 = bias[r0], bv1 = bias[r1];
                const size_t base = (size_t)(cn >> 10) * 1048576 + (cn & 1023);
                *(__half2*)(g_vh + base + (size_t)r0 * 1024) =
                    __float22half2_rn(make_float2(gc.c[mi][ni][0] + bv0, gc.c[mi][ni][1] + bv0));
                *(__half2*)(g_vh + base + (size_t)r1 * 1024) =
                    __float22half2_rn(make_float2(gc.c[mi][ni][2] + bv1, gc.c[mi][ni][3] + bv1));
            } else {
                __half* dst = (z == 0) ? g_qh : g_kh;
                const float bv0 = bias[cn], bv1 = bias[cn + 1];
                const int h = cn >> 6, d = cn & 63;
                const int bi0 = r0 >> 10, l0 = r0 & 1023;
                const int bi1 = r1 >> 10, l1 = r1 & 1023;
                *(__half2*)(dst + (((size_t)(bi0 * Hdim + h)) * Ldim + l0) * Ddim + d) =
                    __float22half2_rn(make_float2(gc.c[mi][ni][0] + bv0, gc.c[mi][ni][1] + bv1));
                *(__half2*)(dst + (((size_t)(bi1 * Hdim + h)) * Ldim + l1) * Ddim + d) =
                    __float22half2_rn(make_float2(gc.c[mi][ni][2] + bv0, gc.c[mi][ni][3] + bv1));
            }
        }
    }
}

// ---------------------------------------------------------------------------
// Output projection: out = merge_heads(g_atth) @ Wo^T + bo (fp32 out)
// ---------------------------------------------------------------------------
__global__ void __launch_bounds__(256) out_gemm(
    const float* __restrict__ bias,
    float* __restrict__ Cout)
{
    extern __shared__ __half smh[];
    const int M0 = blockIdx.y * 128;
    const int N0 = blockIdx.x * 128;
    const int tid = threadIdx.x;
    const int wid = tid >> 5;
    const int lane = tid & 31;
    const int grp = lane >> 2;
    const int tig = lane & 3;
    const int wm = wid >> 2;
    const int wn = wid & 3;

    GemmCoreH gc;
    gc.run(smh,
        [&](int m, int k) {
            const int bi = m >> 10, l = m & 1023;
            const int h = k >> 6, d = k & 63;
            return (const void*)(g_atth + (((size_t)(bi * Hdim + h)) * Ldim + l) * Ddim + d);
        },
        h_wo, M0, N0, tid, wm, wn, lane);

    #pragma unroll
    for (int mi = 0; mi < 4; mi++) {
        #pragma unroll
        for (int ni = 0; ni < 4; ni++) {
            const int r0 = M0 + wm * 64 + mi * 16 + grp;
            const int r1 = r0 + 8;
            const int cn = N0 + wn * 32 + ni * 8 + tig * 2;
            const float bv0 = bias[cn], bv1 = bias[cn + 1];
            *(float2*)(Cout + (size_t)r0 * 1024 + cn) =
                make_float2(gc.c[mi][ni][0] + bv0, gc.c[mi][ni][1] + bv1);
            *(float2*)(Cout + (size_t)r1 * 1024 + cn) =
                make_float2(gc.c[mi][ni][2] + bv0, gc.c[mi][ni][3] + bv1);
        }
    }
}

// ---------------------------------------------------------------------------
// Fused flash attention (fp16 mma, ldmatrix feeds, cp.async pipelined).
// smem: uQh half[128][72], fKh half[64][72], fVh half[64][72],
//       fP fp32[128][68] (prev staging; overlaid by P half[128][136-stride]).
// ---------------------------------------------------------------------------
#define SMEM_FUSED ((128*72 + 64*72 + 64*72) * 2 + 128*68*4)   // 71680 B

__global__ void __launch_bounds__(256, 2) fused_attn(
    const float* __restrict__ prev,
    const int* __restrict__ mask,
    const float* __restrict__ gat,
    float* __restrict__ scores)
{
    extern __shared__ __half smh[];
    __half* uQh = smh;                  // [128][72]
    __half* fKh = uQh + 128 * 72;       // [64][72]  K tile [j][d]
    __half* fVh = fKh + 64 * 72;        // [64][72]  V^T tile [d][j]
    float*  fP  = (float*)(fVh + 64 * 72);  // [128][68] prev fp32
    unsigned* uP = (unsigned*)fP;       // P half2, row stride 68 unsigneds (136 halves)

    const unsigned uQb = (unsigned)__cvta_generic_to_shared(uQh);
    const unsigned uKb = (unsigned)__cvta_generic_to_shared(fKh);
    const unsigned uVb = (unsigned)__cvta_generic_to_shared(fVh);
    const unsigned uPb = (unsigned)__cvta_generic_to_shared(fP);

    const int bh = blockIdx.y;
    const int q0 = blockIdx.x * 128;
    const int tid = threadIdx.x;
    const int w = tid >> 5;
    const int lane = tid & 31;
    const int grp = lane >> 2;
    const int tig = lane & 3;
    const int quad = lane >> 3, r8 = lane & 7;
    const int aoff72  = (((quad & 1) << 3) + r8) * 72 + ((quad >> 1) << 3);
    const int aoff136 = (((quad & 1) << 3) + r8) * 136 + ((quad >> 1) << 3);
    const int boff72  = (((quad >> 1) << 3) + r8) * 72 + ((quad & 1) << 3);
    const int rw0 = w * 16 + grp;
    const int rw1 = rw0 + 8;
    const int gq0 = q0 + rw0;
    const int gq1 = q0 + rw1;

    const __half* qgh = g_qh + (size_t)bh * Ldim * Ddim;
    const __half* kgh = g_kh + (size_t)bh * Ldim * Ddim;
    const __half* vgh = g_vh + (size_t)bh * Ddim * Ldim;  // [d][l]
    const size_t sb = ((size_t)bh << 20);
    const float* prevb = prev + sb + (size_t)(q0 + w * 16) * Ldim;

    auto issueK = [&](int kt) {
        #pragma unroll
        for (int p = 0; p < 2; p++) {
            const int cid = tid + p * 256;
            const int r = cid >> 3;
            const int cc = (cid & 7) << 3;
            cp16(&fKh[r * 72 + cc], kgh + (size_t)(kt + r) * Ddim + cc);
        }
        CP_COMMIT();
    };
    auto issueVP = [&](int kt) {
        #pragma unroll
        for (int p = 0; p < 2; p++) {
            const int cid = tid + p * 256;
            const int r = cid >> 3;
            const int cc = (cid & 7) << 3;
            cp16(&fVh[r * 72 + cc], vgh + (size_t)r * Ldim + kt + cc);
        }
        #pragma unroll
        for (int j = 0; j < 8; j++) {
            const int cid = j * 32 + lane;
            const int r = cid >> 4;
            const int c4 = (cid & 15) << 2;
            cp16(&fP[(w * 16 + r) * 68 + c4], prevb + (size_t)r * Ldim + kt + c4);
        }
        CP_COMMIT();
    };

    issueK(0);
    issueVP(0);

    // Q tile once: 128 x 64 halves, direct uint4 copies
    #pragma unroll
    for (int p = 0; p < 4; p++) {
        const int cid = tid + p * 256;
        const int m = cid >> 3;
        const int cc = (cid & 7) << 3;
        *(uint4*)&uQh[m * 72 + cc] = *(const uint4*)(qgh + (size_t)(q0 + m) * Ddim + cc);
    }

    const int vl0 = mask[(bh & 3) * Ldim + gq0];
    const int vl1 = mask[(bh & 3) * Ldim + gq1];
    const float gv = 1.f / (1.f + __expf(-gat[0]));
    const float og = 1.f - gv;

    float o[8][4];
    #pragma unroll
    for (int ni = 0; ni < 8; ni++)
        #pragma unroll
        for (int r = 0; r < 4; r++) o[ni][r] = 0.f;
    float mi0 = -1e30f, mi1 = -1e30f, li0 = 0.f, li1 = 0.f;

    for (int kt = 0; kt < Ldim; kt += 64) {
        const bool more = (kt + 64 < Ldim);

        CP_WAIT1();          // K[t] ready
        __syncthreads();

        // S = Q @ K^T : 4 k-steps of 16
        float cs[8][4];
        #pragma unroll
        for (int ni = 0; ni < 8; ni++)
            #pragma unroll
            for (int r = 0; r < 4; r++) cs[ni][r] = 0.f;

        #pragma unroll
        for (int ks = 0; ks < 4; ks++) {
            const int kk = ks * 16;
            unsigned a0, a1, a2, a3;
            ldsm4(a0, a1, a2, a3, uQb + (unsigned)(w * 16 * 72 + kk + aoff72) * 2);
            unsigned bf[8][2];
            #pragma unroll
            for (int np = 0; np < 4; np++)
                ldsm4(bf[2*np][0], bf[2*np][1], bf[2*np+1][0], bf[2*np+1][1],
                      uKb + (unsigned)(np * 16 * 72 + kk + boff72) * 2);
            #pragma unroll
            for (int ni = 0; ni < 8; ni++)
                mma_f16(cs[ni][0], cs[ni][1], cs[ni][2], cs[ni][3],
                        a0, a1, a2, a3, bf[ni][0], bf[ni][1]);
        }
        __syncthreads();               // K buffer free
        if (more) issueK(kt + 64);

        if (more) CP_WAIT1(); else CP_WAIT0();   // {V,prev}[t] ready
        __syncwarp();                  // prev rows warp-local

        // blend with prev, write scores, mask+scale
        float m0 = -1e30f, m1 = -1e30f;
        #pragma unroll
        for (int ni = 0; ni < 8; ni++) {
            const int cl = ni * 8 + tig * 2;
            const int col = kt + cl;
            const float2 p0 = *(const float2*)&fP[rw0 * 68 + cl];
            const float2 p1 = *(const float2*)&fP[rw1 * 68 + cl];
            const float b00 = p0.x * gv + og * cs[ni][0];
            const float b01 = p0.y * gv + og * cs[ni][1];
            const float b10 = p1.x * gv + og * cs[ni][2];
            const float b11 = p1.y * gv + og * cs[ni][3];
            const size_t i0 = sb + (size_t)gq0 * Ldim + col;
            const size_t i1 = sb + (size_t)gq1 * Ldim + col;
            *(float2*)(scores + i0) = make_float2(b00, b01);
            *(float2*)(scores + i1) = make_float2(b10, b11);
            cs[ni][0] = (col     < vl0) ? b00 * 0.125f : -1e30f;
            cs[ni][1] = (col + 1 < vl0) ? b01 * 0.125f : -1e30f;
            cs[ni][2] = (col     < vl1) ? b10 * 0.125f : -1e30f;
            cs[ni][3] = (col + 1 < vl1) ? b11 * 0.125f : -1e30f;
            m0 = fmaxf(m0, fmaxf(cs[ni][0], cs[ni][1]));
            m1 = fmaxf(m1, fmaxf(cs[ni][2], cs[ni][3]));
        }
        m0 = fmaxf(m0, __shfl_xor_sync(0xffffffffu, m0, 1));
        m0 = fmaxf(m0, __shfl_xor_sync(0xffffffffu, m0, 2));
        m1 = fmaxf(m1, __shfl_xor_sync(0xffffffffu, m1, 1));
        m1 = fmaxf(m1, __shfl_xor_sync(0xffffffffu, m1, 2));

        const float mn0 = fmaxf(mi0, m0);
        const float mn1 = fmaxf(mi1, m1);
        const float cr0 = __expf(mi0 - mn0);
        const float cr1 = __expf(mi1 - mn1);
        li0 *= cr0; li1 *= cr1;
        #pragma unroll
        for (int ni = 0; ni < 8; ni++) {
            o[ni][0] *= cr0; o[ni][1] *= cr0;
            o[ni][2] *= cr1; o[ni][3] *= cr1;
        }
        mi0 = mn0; mi1 = mn1;

        // P = exp(s - m) -> half2 into uP (stride 68 unsigneds, warp-local rows)
        #pragma unroll
        for (int ni = 0; ni < 8; ni++) {
            const float p00 = __expf(cs[ni][0] - mn0);
            const float p01 = __expf(cs[ni][1] - mn0);
            const float p10 = __expf(cs[ni][2] - mn1);
            const float p11 = __expf(cs[ni][3] - mn1);
            li0 += p00 + p01;
            li1 += p10 + p11;
            const int pc = ni * 4 + tig;
            uP[rw0 * 68 + pc] = f2h2(p00, p01);
            uP[rw1 * 68 + pc] = f2h2(p10, p11);
        }
        __syncwarp();

        // O += P @ V : ldmatrix A from uP (stride 136 halves), B from fVh
        #pragma unroll
        for (int ks = 0; ks < 4; ks++) {
            const int kk = ks * 16;
            unsigned a0, a1, a2, a3;
            ldsm4(a0, a1, a2, a3, uPb + (unsigned)(w * 16 * 136 + kk + aoff136) * 2);
            unsigned bf[8][2];
            #pragma unroll
            for (int np = 0; np < 4; np++)
                ldsm4(bf[2*np][0], bf[2*np][1], bf[2*np+1][0], bf[2*np+1][1],
                      uVb + (unsigned)(np * 16 * 72 + kk + boff72) * 2);
            #pragma unroll
            for (int ni = 0; ni < 8; ni++)
                mma_f16(o[ni][0], o[ni][1], o[ni][2], o[ni][3],
                        a0, a1, a2, a3, bf[ni][0], bf[ni][1]);
        }
        __syncthreads();               // V + uP buffers free
        if (more) issueVP(kt + 64);
    }

    li0 += __shfl_xor_sync(0xffffffffu, li0, 1);
    li0 += __shfl_xor_sync(0xffffffffu, li0, 2);
    li1 += __shfl_xor_sync(0xffffffffu, li1, 1);
    li1 += __shfl_xor_sync(0xffffffffu, li1, 2);
    const float inv0 = 1.f / li0;
    const float inv1 = 1.f / li1;

    __half* ab = g_atth + (size_t)bh * Ldim * Ddim;
    #pragma unroll
    for (int ni = 0; ni < 8; ni++) {
        const int d = ni * 8 + tig * 2;
        *(__half2*)(ab + (size_t)gq0 * Ddim + d) =
            __float22half2_rn(make_float2(o[ni][0] * inv0, o[ni][1] * inv0));
        *(__half2*)(ab + (size_t)gq1 * Ddim + d) =
            __float22half2_rn(make_float2(o[ni][2] * inv1, o[ni][3] * inv1));
    }
}

// ---------------------------------------------------------------------------
// Launch.  Inputs: queries, keys, values, prev, mask(int32),
//   Wq_w, Wq_b, Wk_w, Wk_b, Wv_w, Wv_b, Wo_w, Wo_b, gat
// Output: [out (4M floats) | scores (64M floats)]
// ---------------------------------------------------------------------------
extern "C" void kernel_launch(void* const* d_in, const int* in_sizes, int n_in,
                              void* d_out, int out_size)
{
    (void)in_sizes; (void)n_in; (void)out_size;
    const float* queries = (const float*)d_in[0];
    const float* keys    = (const float*)d_in[1];
    const float* values  = (const float*)d_in[2];
    const float* prev    = (const float*)d_in[3];
    const int*   mask    = (const int*)d_in[4];
    const float* Wq_w = (const float*)d_in[5];
    const float* Wq_b = (const float*)d_in[6];
    const float* Wk_w = (const float*)d_in[7];
    const float* Wk_b = (const float*)d_in[8];
    const float* Wv_w = (const float*)d_in[9];
    const float* Wv_b = (const float*)d_in[10];
    const float* Wo_w = (const float*)d_in[11];
    const float* Wo_b = (const float*)d_in[12];
    const float* gat  = (const float*)d_in[13];

    float* out    = (float*)d_out;
    float* scores = out + (size_t)Bdim * Ldim * HIDdim;

    cudaFuncSetAttribute(fused_attn,
                         cudaFuncAttributeMaxDynamicSharedMemorySize, SMEM_FUSED);
    cudaFuncSetAttribute(qkv_gemm,
                         cudaFuncAttributeMaxDynamicSharedMemorySize, GEMM_SMEM);
    cudaFuncSetAttribute(out_gemm,
                         cudaFuncAttributeMaxDynamicSharedMemorySize, GEMM_SMEM);

    conv_half<<<16384, 256>>>(queries, keys, values, Wq_w, Wk_w, Wv_w, Wo_w);

    qkv_gemm<<<768, 256, GEMM_SMEM>>>(Wq_b, Wk_b, Wv_b);

    dim3 gf(8, 64);
    fused_attn<<<gf, 256, SMEM_FUSED>>>(prev, mask, gat, scores);

    dim3 gproj(8, 32);
    out_gemm<<<gproj, 256, GEMM_SMEM>>>(Wo_b, out);
}

// round 10
// speedup vs baseline: 1.9031x; 1.0056x over previous
#include <cuda_runtime.h>
#include <cuda_fp16.h>
#include <math.h>

#define Bdim 4
#define Ldim 1024
#define Hdim 16
#define Ddim 64
#define HIDdim 1024
#define BHdim (Bdim*Hdim)

// fp16 copies of GEMM operands (converted once at start)
__device__ __half h_qry[4194304];
__device__ __half h_key[4194304];
__device__ __half h_val[4194304];
__device__ __half h_wq[1048576];
__device__ __half h_wk[1048576];
__device__ __half h_wv[1048576];
__device__ __half h_wo[1048576];
// fp16 intermediates
__device__ __half g_qh[4194304];   // [BH][L][D]
__device__ __half g_kh[4194304];   // [BH][L][D]
__device__ __half g_vh[4194304];   // TRANSPOSED [BH][D][L]
__device__ __half g_atth[4194304]; // [BH][L][D]

__device__ __forceinline__ unsigned f2h2(float lo, float hi) {
    __half2 h = __float22half2_rn(make_float2(lo, hi));
    return *(unsigned*)&h;
}

__device__ __forceinline__ void mma_f16(
    float& c0, float& c1, float& c2, float& c3,
    unsigned a0, unsigned a1, unsigned a2, unsigned a3,
    unsigned b0, unsigned b1)
{
    asm volatile(
        "mma.sync.aligned.m16n8k16.row.col.f32.f16.f16.f32 "
        "{%0,%1,%2,%3}, {%4,%5,%6,%7}, {%8,%9}, {%0,%1,%2,%3};"
        : "+f"(c0), "+f"(c1), "+f"(c2), "+f"(c3)
        : "r"(a0), "r"(a1), "r"(a2), "r"(a3), "r"(b0), "r"(b1));
}

__device__ __forceinline__ void ldsm4(
    unsigned& r0, unsigned& r1, unsigned& r2, unsigned& r3, unsigned addr)
{
    asm volatile("ldmatrix.sync.aligned.m8n8.x4.shared.b16 {%0,%1,%2,%3}, [%4];"
        : "=r"(r0), "=r"(r1), "=r"(r2), "=r"(r3) : "r"(addr));
}

__device__ __forceinline__ void cp16(void* smem, const void* gmem) {
    unsigned sa = (unsigned)__cvta_generic_to_shared(smem);
    asm volatile("cp.async.cg.shared.global [%0], [%1], 16;" :: "r"(sa), "l"(gmem));
}
__device__ __forceinline__ void stcs2(float* p, float x, float y) {
    asm volatile("st.global.cs.v2.f32 [%0], {%1,%2};" :: "l"(p), "f"(x), "f"(y) : "memory");
}
#define CP_COMMIT() asm volatile("cp.async.commit_group;")
#define CP_WAIT0()  asm volatile("cp.async.wait_group 0;")
#define CP_WAIT1()  asm volatile("cp.async.wait_group 1;")

// ---------------------------------------------------------------------------
// fp32 -> fp16 conversion of all GEMM operands. 16M floats, float4/thread.
// ---------------------------------------------------------------------------
__global__ void __launch_bounds__(256) conv_half(
    const float* __restrict__ q, const float* __restrict__ k,
    const float* __restrict__ v,
    const float* __restrict__ wq, const float* __restrict__ wk,
    const float* __restrict__ wv, const float* __restrict__ wo)
{
    const size_t idx = (size_t)blockIdx.x * 256 + threadIdx.x;
    const size_t e = idx * 4;
    const float* src;
    __half* dst;
    size_t off;
    if (e < 4194304)        { src = q;  dst = h_qry; off = e; }
    else if (e < 8388608)   { src = k;  dst = h_key; off = e - 4194304; }
    else if (e < 12582912)  { src = v;  dst = h_val; off = e - 8388608; }
    else {
        const size_t e2 = e - 12582912;
        const int s = (int)(e2 >> 20);
        off = e2 & 1048575;
        src = (s == 0) ? wq : (s == 1) ? wk : (s == 2) ? wv : wo;
        dst = (s == 0) ? h_wq : (s == 1) ? h_wk : (s == 2) ? h_wv : h_wo;
    }
    const float4 f = *(const float4*)(src + off);
    *(__half2*)(dst + off)     = __float22half2_rn(make_float2(f.x, f.y));
    *(__half2*)(dst + off + 2) = __float22half2_rn(make_float2(f.z, f.w));
}

// ---------------------------------------------------------------------------
// fp16 GEMM core: block tile 64x128, 128 threads (4 warps, warp tile 64x32),
// K=1024, k-tile 64 halves, double-buffered cp.async, ldmatrix feeds.
// smem rows 72 halves (144B) conflict-free.
// ---------------------------------------------------------------------------
#define GEMM_SMEM ((2*64*72 + 2*128*72) * 2)   // 55296 B

struct GemmCoreH {
    float c[4][4][4];

    template<class SrcA>
    __device__ __forceinline__ void run(
        __half* smh, SrcA srcA, const __half* __restrict__ W,
        int M0, int N0, int tid, int wn, int lane)
    {
        __half* As = smh;                 // [2][64][72]
        __half* Ws = smh + 2 * 64 * 72;   // [2][128][72]
        const unsigned uAs = (unsigned)__cvta_generic_to_shared(As);
        const unsigned uWs = (unsigned)__cvta_generic_to_shared(Ws);
        const int quad = lane >> 3, r8 = lane & 7;
        const int aoff = (((quad & 1) << 3) + r8) * 72 + ((quad >> 1) << 3);
        const int boff = (((quad >> 1) << 3) + r8) * 72 + ((quad & 1) << 3);

        #pragma unroll
        for (int mi = 0; mi < 4; mi++)
            #pragma unroll
            for (int ni = 0; ni < 4; ni++)
                #pragma unroll
                for (int r = 0; r < 4; r++) c[mi][ni][r] = 0.f;

        auto issue = [&](int kt, int s) {
            const int k0 = kt * 64;
            #pragma unroll
            for (int p = 0; p < 4; p++) {
                const int cid = tid + p * 128;
                const int m = cid >> 3;
                const int cc = (cid & 7) << 3;
                cp16(&As[(size_t)(s * 64 + m) * 72 + cc], srcA(M0 + m, k0 + cc));
            }
            #pragma unroll
            for (int p = 0; p < 8; p++) {
                const int cid = tid + p * 128;
                const int m = cid >> 3;
                const int cc = (cid & 7) << 3;
                cp16(&Ws[(size_t)(s * 128 + m) * 72 + cc],
                     W + (size_t)(N0 + m) * 1024 + k0 + cc);
            }
            CP_COMMIT();
        };

        issue(0, 0);
        for (int kt = 0; kt < 16; kt++) {
            const int s = kt & 1;
            if (kt + 1 < 16) { issue(kt + 1, s ^ 1); CP_WAIT1(); }
            else             { CP_WAIT0(); }
            __syncthreads();

            const unsigned aBase = uAs + (unsigned)((s * 64) * 72 + aoff) * 2;
            const unsigned bBase = uWs + (unsigned)((s * 128 + wn * 32) * 72 + boff) * 2;
            #pragma unroll
            for (int ks = 0; ks < 4; ks++) {
                const int kk = ks * 16;
                unsigned af[4][4], bf[4][2];
                #pragma unroll
                for (int mi = 0; mi < 4; mi++)
                    ldsm4(af[mi][0], af[mi][1], af[mi][2], af[mi][3],
                          aBase + (unsigned)(mi * 16 * 72 + kk) * 2);
                #pragma unroll
                for (int np = 0; np < 2; np++)
                    ldsm4(bf[2*np][0], bf[2*np][1], bf[2*np+1][0], bf[2*np+1][1],
                          bBase + (unsigned)(np * 16 * 72 + kk) * 2);
                #pragma unroll
                for (int mi = 0; mi < 4; mi++)
                    #pragma unroll
                    for (int ni = 0; ni < 4; ni++)
                        mma_f16(c[mi][ni][0], c[mi][ni][1], c[mi][ni][2], c[mi][ni][3],
                                af[mi][0], af[mi][1], af[mi][2], af[mi][3],
                                bf[ni][0], bf[ni][1]);
            }
            __syncthreads();
        }
    }
};

// ---------------------------------------------------------------------------
// Merged Q/K/V projection: 1536 blocks of 128 threads, z = g>>9.
//   z=0: g_qh = qry @ Wq^T + bq (split-head); z=1: g_kh likewise;
//   z=2: g_vh^T = Wv @ val^T + bv (transposed, bias by ROW)
// ---------------------------------------------------------------------------
__global__ void __launch_bounds__(128, 4) qkv_gemm(
    const float* __restrict__ Wq_b, const float* __restrict__ Wk_b,
    const float* __restrict__ Wv_b)
{
    extern __shared__ __half smh[];
    const int g = blockIdx.x;
    const int z = g >> 9;
    const int r = g & 511;
    const int tid = threadIdx.x;
    const int lane = tid & 31;
    const int grp = lane >> 2;
    const int tig = lane & 3;
    const int wn = tid >> 5;

    const __half *A, *W;
    const float* bias;
    int M0, N0;
    if (z == 0)      { A = h_qry; W = h_wq; bias = Wq_b; M0 = (r >> 3) * 64; N0 = (r & 7) * 128; }
    else if (z == 1) { A = h_key; W = h_wk; bias = Wk_b; M0 = (r >> 3) * 64; N0 = (r & 7) * 128; }
    else             { A = h_wv;  W = h_val; bias = Wv_b; M0 = (r & 15) * 64; N0 = (r >> 4) * 128; }

    GemmCoreH gc;
    gc.run(smh, [&](int m, int k) { return (const void*)(A + (size_t)m * 1024 + k); },
           W, M0, N0, tid, wn, lane);

    #pragma unroll
    for (int mi = 0; mi < 4; mi++) {
        #pragma unroll
        for (int ni = 0; ni < 4; ni++) {
            const int r0 = M0 + mi * 16 + grp;
            const int r1 = r0 + 8;
            const int cn = N0 + wn * 32 + ni * 8 + tig * 2;
            if (z == 2) {
                const float bv0 = bias[r0], bv1 = bias[r1];
                const size_t base = (size_t)(cn >> 10) * 1048576 + (cn & 1023);
                *(__half2*)(g_vh + base + (size_t)r0 * 1024) =
                    __float22half2_rn(make_float2(gc.c[mi][ni][0] + bv0, gc.c[mi][ni][1] + bv0));
                *(__half2*)(g_vh + base + (size_t)r1 * 1024) =
                    __float22half2_rn(make_float2(gc.c[mi][ni][2] + bv1, gc.c[mi][ni][3] + bv1));
            } else {
                __half* dst = (z == 0) ? g_qh : g_kh;
                const float bv0 = bias[cn], bv1 = bias[cn + 1];
                const int h = cn >> 6, d = cn & 63;
                const int bi0 = r0 >> 10, l0 = r0 & 1023;
                const int bi1 = r1 >> 10, l1 = r1 & 1023;
                *(__half2*)(dst + (((size_t)(bi0 * Hdim + h)) * Ldim + l0) * Ddim + d) =
                    __float22half2_rn(make_float2(gc.c[mi][ni][0] + bv0, gc.c[mi][ni][1] + bv1));
                *(__half2*)(dst + (((size_t)(bi1 * Hdim + h)) * Ldim + l1) * Ddim + d) =
                    __float22half2_rn(make_float2(gc.c[mi][ni][2] + bv0, gc.c[mi][ni][3] + bv1));
            }
        }
    }
}

// ---------------------------------------------------------------------------
// Output projection: out = merge_heads(g_atth) @ Wo^T + bo (fp32 out)
// ---------------------------------------------------------------------------
__global__ void __launch_bounds__(128, 4) out_gemm(
    const float* __restrict__ bias,
    float* __restrict__ Cout)
{
    extern __shared__ __half smh[];
    const int M0 = blockIdx.y * 64;
    const int N0 = blockIdx.x * 128;
    const int tid = threadIdx.x;
    const int lane = tid & 31;
    const int grp = lane >> 2;
    const int tig = lane & 3;
    const int wn = tid >> 5;

    GemmCoreH gc;
    gc.run(smh,
        [&](int m, int k) {
            const int bi = m >> 10, l = m & 1023;
            const int h = k >> 6, d = k & 63;
            return (const void*)(g_atth + (((size_t)(bi * Hdim + h)) * Ldim + l) * Ddim + d);
        },
        h_wo, M0, N0, tid, wn, lane);

    #pragma unroll
    for (int mi = 0; mi < 4; mi++) {
        #pragma unroll
        for (int ni = 0; ni < 4; ni++) {
            const int r0 = M0 + mi * 16 + grp;
            const int r1 = r0 + 8;
            const int cn = N0 + wn * 32 + ni * 8 + tig * 2;
            const float bv0 = bias[cn], bv1 = bias[cn + 1];
            *(float2*)(Cout + (size_t)r0 * 1024 + cn) =
                make_float2(gc.c[mi][ni][0] + bv0, gc.c[mi][ni][1] + bv1);
            *(float2*)(Cout + (size_t)r1 * 1024 + cn) =
                make_float2(gc.c[mi][ni][2] + bv0, gc.c[mi][ni][3] + bv1);
        }
    }
}

// ---------------------------------------------------------------------------
// Fused flash attention: 64-query blocks, 128 threads (4 warps x 16 rows).
// RACE FIX vs R9: __syncthreads() after the VP wait, so every warp's
// cp.async V-tile writes are complete & visible before ANY warp's PV mma.
// smem: uQh half[64][72], fKh half[64][72], fVh half[64][72],
//       fP fp32[64][68] (prev staging; overlaid by P half, stride 136).
// ---------------------------------------------------------------------------
#define SMEM_FUSED ((64*72 * 3) * 2 + 64*68*4)   // 45056 B

__global__ void __launch_bounds__(128, 4) fused_attn(
    const float* __restrict__ prev,
    const int* __restrict__ mask,
    const float* __restrict__ gat,
    float* __restrict__ scores)
{
    extern __shared__ __half smh[];
    __half* uQh = smh;                  // [64][72]
    __half* fKh = uQh + 64 * 72;        // [64][72]  K tile [j][d]
    __half* fVh = fKh + 64 * 72;        // [64][72]  V^T tile [d][j]
    float*  fP  = (float*)(fVh + 64 * 72);  // [64][68] prev fp32
    unsigned* uP = (unsigned*)fP;       // P half2, row stride 68 unsigneds

    const unsigned uQb = (unsigned)__cvta_generic_to_shared(uQh);
    const unsigned uKb = (unsigned)__cvta_generic_to_shared(fKh);
    const unsigned uVb = (unsigned)__cvta_generic_to_shared(fVh);
    const unsigned uPb = (unsigned)__cvta_generic_to_shared(fP);

    const int bh = blockIdx.y;
    const int q0 = blockIdx.x * 64;
    const int tid = threadIdx.x;
    const int w = tid >> 5;
    const int lane = tid & 31;
    const int grp = lane >> 2;
    const int tig = lane & 3;
    const int quad = lane >> 3, r8 = lane & 7;
    const int aoff72  = (((quad & 1) << 3) + r8) * 72 + ((quad >> 1) << 3);
    const int aoff136 = (((quad & 1) << 3) + r8) * 136 + ((quad >> 1) << 3);
    const int boff72  = (((quad >> 1) << 3) + r8) * 72 + ((quad & 1) << 3);
    const int rw0 = w * 16 + grp;
    const int rw1 = rw0 + 8;
    const int gq0 = q0 + rw0;
    const int gq1 = q0 + rw1;

    const __half* qgh = g_qh + (size_t)bh * Ldim * Ddim;
    const __half* kgh = g_kh + (size_t)bh * Ldim * Ddim;
    const __half* vgh = g_vh + (size_t)bh * Ddim * Ldim;  // [d][l]
    const size_t sb = ((size_t)bh << 20);
    const float* prevb = prev + sb + (size_t)(q0 + w * 16) * Ldim;

    auto issueK = [&](int kt) {
        #pragma unroll
        for (int p = 0; p < 4; p++) {
            const int cid = tid + p * 128;
            const int r = cid >> 3;
            const int cc = (cid & 7) << 3;
            cp16(&fKh[r * 72 + cc], kgh + (size_t)(kt + r) * Ddim + cc);
        }
        CP_COMMIT();
    };
    auto issueVP = [&](int kt) {
        #pragma unroll
        for (int p = 0; p < 4; p++) {
            const int cid = tid + p * 128;
            const int r = cid >> 3;
            const int cc = (cid & 7) << 3;
            cp16(&fVh[r * 72 + cc], vgh + (size_t)r * Ldim + kt + cc);
        }
        #pragma unroll
        for (int j = 0; j < 8; j++) {
            const int cid = j * 32 + lane;
            const int r = cid >> 4;
            const int c4 = (cid & 15) << 2;
            cp16(&fP[(w * 16 + r) * 68 + c4], prevb + (size_t)r * Ldim + kt + c4);
        }
        CP_COMMIT();
    };

    issueK(0);
    issueVP(0);

    // Q tile once: 64 x 64 halves
    #pragma unroll
    for (int p = 0; p < 4; p++) {
        const int cid = tid + p * 128;
        const int m = cid >> 3;
        const int cc = (cid & 7) << 3;
        *(uint4*)&uQh[m * 72 + cc] = *(const uint4*)(qgh + (size_t)(q0 + m) * Ddim + cc);
    }

    const int vl0 = mask[(bh & 3) * Ldim + gq0];
    const int vl1 = mask[(bh & 3) * Ldim + gq1];
    const float gv = 1.f / (1.f + __expf(-gat[0]));
    const float og = 1.f - gv;

    float o[8][4];
    #pragma unroll
    for (int ni = 0; ni < 8; ni++)
        #pragma unroll
        for (int r = 0; r < 4; r++) o[ni][r] = 0.f;
    float mi0 = -1e30f, mi1 = -1e30f, li0 = 0.f, li1 = 0.f;

    for (int kt = 0; kt < Ldim; kt += 64) {
        const bool more = (kt + 64 < Ldim);

        CP_WAIT1();          // K[t] ready (this thread's copies)
        __syncthreads();     // block-wide K visibility

        // S = Q @ K^T
        float cs[8][4];
        #pragma unroll
        for (int ni = 0; ni < 8; ni++)
            #pragma unroll
            for (int r = 0; r < 4; r++) cs[ni][r] = 0.f;

        #pragma unroll
        for (int ks = 0; ks < 4; ks++) {
            const int kk = ks * 16;
            unsigned a0, a1, a2, a3;
            ldsm4(a0, a1, a2, a3, uQb + (unsigned)(w * 16 * 72 + kk + aoff72) * 2);
            unsigned bf[8][2];
            #pragma unroll
            for (int np = 0; np < 4; np++)
                ldsm4(bf[2*np][0], bf[2*np][1], bf[2*np+1][0], bf[2*np+1][1],
                      uKb + (unsigned)(np * 16 * 72 + kk + boff72) * 2);
            #pragma unroll
            for (int ni = 0; ni < 8; ni++)
                mma_f16(cs[ni][0], cs[ni][1], cs[ni][2], cs[ni][3],
                        a0, a1, a2, a3, bf[ni][0], bf[ni][1]);
        }
        __syncthreads();               // K buffer free
        if (more) issueK(kt + 64);

        if (more) CP_WAIT1(); else CP_WAIT0();   // {V,prev}[t]: own copies done
        __syncthreads();               // RACE FIX: all warps' V visible block-wide

        // blend with prev, write scores (streaming), mask+scale
        float m0 = -1e30f, m1 = -1e30f;
        #pragma unroll
        for (int ni = 0; ni < 8; ni++) {
            const int cl = ni * 8 + tig * 2;
            const int col = kt + cl;
            const float2 p0 = *(const float2*)&fP[rw0 * 68 + cl];
            const float2 p1 = *(const float2*)&fP[rw1 * 68 + cl];
            const float b00 = p0.x * gv + og * cs[ni][0];
            const float b01 = p0.y * gv + og * cs[ni][1];
            const float b10 = p1.x * gv + og * cs[ni][2];
            const float b11 = p1.y * gv + og * cs[ni][3];
            stcs2(scores + sb + (size_t)gq0 * Ldim + col, b00, b01);
            stcs2(scores + sb + (size_t)gq1 * Ldim + col, b10, b11);
            cs[ni][0] = (col     < vl0) ? b00 * 0.125f : -1e30f;
            cs[ni][1] = (col + 1 < vl0) ? b01 * 0.125f : -1e30f;
            cs[ni][2] = (col     < vl1) ? b10 * 0.125f : -1e30f;
            cs[ni][3] = (col + 1 < vl1) ? b11 * 0.125f : -1e30f;
            m0 = fmaxf(m0, fmaxf(cs[ni][0], cs[ni][1]));
            m1 = fmaxf(m1, fmaxf(cs[ni][2], cs[ni][3]));
        }
        m0 = fmaxf(m0, __shfl_xor_sync(0xffffffffu, m0, 1));
        m0 = fmaxf(m0, __shfl_xor_sync(0xffffffffu, m0, 2));
        m1 = fmaxf(m1, __shfl_xor_sync(0xffffffffu, m1, 1));
        m1 = fmaxf(m1, __shfl_xor_sync(0xffffffffu, m1, 2));

        const float mn0 = fmaxf(mi0, m0);
        const float mn1 = fmaxf(mi1, m1);
        const float cr0 = __expf(mi0 - mn0);
        const float cr1 = __expf(mi1 - mn1);
        li0 *= cr0; li1 *= cr1;
        #pragma unroll
        for (int ni = 0; ni < 8; ni++) {
            o[ni][0] *= cr0; o[ni][1] *= cr0;
            o[ni][2] *= cr1; o[ni][3] *= cr1;
        }
        mi0 = mn0; mi1 = mn1;

        // P = exp(s - m) -> half2 into uP (warp-local rows)
        #pragma unroll
        for (int ni = 0; ni < 8; ni++) {
            const float p00 = __expf(cs[ni][0] - mn0);
            const float p01 = __expf(cs[ni][1] - mn0);
            const float p10 = __expf(cs[ni][2] - mn1);
            const float p11 = __expf(cs[ni][3] - mn1);
            li0 += p00 + p01;
            li1 += p10 + p11;
            const int pc = ni * 4 + tig;
            uP[rw0 * 68 + pc] = f2h2(p00, p01);
            uP[rw1 * 68 + pc] = f2h2(p10, p11);
        }
        __syncwarp();

        // O += P @ V (P rows warp-local; V block-visible via the sync above)
        #pragma unroll
        for (int ks = 0; ks < 4; ks++) {
            const int kk = ks * 16;
            unsigned a0, a1, a2, a3;
            ldsm4(a0, a1, a2, a3, uPb + (unsigned)(w * 16 * 136 + kk + aoff136) * 2);
            unsigned bf[8][2];
            #pragma unroll
            for (int np = 0; np < 4; np++)
                ldsm4(bf[2*np][0], bf[2*np][1], bf[2*np+1][0], bf[2*np+1][1],
                      uVb + (unsigned)(np * 16 * 72 + kk + boff72) * 2);
            #pragma unroll
            for (int ni = 0; ni < 8; ni++)
                mma_f16(o[ni][0], o[ni][1], o[ni][2], o[ni][3],
                        a0, a1, a2, a3, bf[ni][0], bf[ni][1]);
        }
        __syncthreads();               // V + uP buffers free
        if (more) issueVP(kt + 64);
    }

    li0 += __shfl_xor_sync(0xffffffffu, li0, 1);
    li0 += __shfl_xor_sync(0xffffffffu, li0, 2);
    li1 += __shfl_xor_sync(0xffffffffu, li1, 1);
    li1 += __shfl_xor_sync(0xffffffffu, li1, 2);
    const float inv0 = 1.f / li0;
    const float inv1 = 1.f / li1;

    __half* ab = g_atth + (size_t)bh * Ldim * Ddim;
    #pragma unroll
    for (int ni = 0; ni < 8; ni++) {
        const int d = ni * 8 + tig * 2;
        *(__half2*)(ab + (size_t)gq0 * Ddim + d) =
            __float22half2_rn(make_float2(o[ni][0] * inv0, o[ni][1] * inv0));
        *(__half2*)(ab + (size_t)gq1 * Ddim + d) =
            __float22half2_rn(make_float2(o[ni][2] * inv1, o[ni][3] * inv1));
    }
}

// ---------------------------------------------------------------------------
// Launch.  Inputs: queries, keys, values, prev, mask(int32),
//   Wq_w, Wq_b, Wk_w, Wk_b, Wv_w, Wv_b, Wo_w, Wo_b, gat
// Output: [out (4M floats) | scores (64M floats)]
// ---------------------------------------------------------------------------
extern "C" void kernel_launch(void* const* d_in, const int* in_sizes, int n_in,
                              void* d_out, int out_size)
{
    (void)in_sizes; (void)n_in; (void)out_size;
    const float* queries = (const float*)d_in[0];
    const float* keys    = (const float*)d_in[1];
    const float* values  = (const float*)d_in[2];
    const float* prev    = (const float*)d_in[3];
    const int*   mask    = (const int*)d_in[4];
    const float* Wq_w = (const float*)d_in[5];
    const float* Wq_b = (const float*)d_in[6];
    const float* Wk_w = (const float*)d_in[7];
    const float* Wk_b = (const float*)d_in[8];
    const float* Wv_w = (const float*)d_in[9];
    const float* Wv_b = (const float*)d_in[10];
    const float* Wo_w = (const float*)d_in[11];
    const float* Wo_b = (const float*)d_in[12];
    const float* gat  = (const float*)d_in[13];

    float* out    = (float*)d_out;
    float* scores = out + (size_t)Bdim * Ldim * HIDdim;

    cudaFuncSetAttribute(fused_attn,
                         cudaFuncAttributeMaxDynamicSharedMemorySize, SMEM_FUSED);
    cudaFuncSetAttribute(qkv_gemm,
                         cudaFuncAttributeMaxDynamicSharedMemorySize, GEMM_SMEM);
    cudaFuncSetAttribute(out_gemm,
                         cudaFuncAttributeMaxDynamicSharedMemorySize, GEMM_SMEM);

    conv_half<<<16384, 256>>>(queries, keys, values, Wq_w, Wk_w, Wv_w, Wo_w);

    qkv_gemm<<<1536, 128, GEMM_SMEM>>>(Wq_b, Wk_b, Wv_b);

    dim3 gf(16, 64);
    fused_attn<<<gf, 128, SMEM_FUSED>>>(prev, mask, gat, scores);

    dim3 gproj(8, 64);
    out_gemm<<<gproj, 128, GEMM_SMEM>>>(Wo_b, out);
}

// round 11
// speedup vs baseline: 2.0589x; 1.0818x over previous
#include <cuda_runtime.h>
#include <cuda_fp16.h>
#include <math.h>

#define Bdim 4
#define Ldim 1024
#define Hdim 16
#define Ddim 64
#define HIDdim 1024
#define BHdim (Bdim*Hdim)

// fp16 copies of GEMM operands (converted once at start)
__device__ __half h_qry[4194304];
__device__ __half h_key[4194304];
__device__ __half h_val[4194304];
__device__ __half h_wq[1048576];
__device__ __half h_wk[1048576];
__device__ __half h_wv[1048576];
__device__ __half h_wo[1048576];
// fp16 intermediates
__device__ __half g_qh[4194304];   // [BH][L][D]
__device__ __half g_kh[4194304];   // [BH][L][D]
__device__ __half g_vh[4194304];   // TRANSPOSED [BH][D][L]
__device__ __half g_atth[4194304]; // [BH][L][D]

__device__ __forceinline__ unsigned f2h2(float lo, float hi) {
    __half2 h = __float22half2_rn(make_float2(lo, hi));
    return *(unsigned*)&h;
}

__device__ __forceinline__ void mma_f16(
    float& c0, float& c1, float& c2, float& c3,
    unsigned a0, unsigned a1, unsigned a2, unsigned a3,
    unsigned b0, unsigned b1)
{
    asm volatile(
        "mma.sync.aligned.m16n8k16.row.col.f32.f16.f16.f32 "
        "{%0,%1,%2,%3}, {%4,%5,%6,%7}, {%8,%9}, {%0,%1,%2,%3};"
        : "+f"(c0), "+f"(c1), "+f"(c2), "+f"(c3)
        : "r"(a0), "r"(a1), "r"(a2), "r"(a3), "r"(b0), "r"(b1));
}

__device__ __forceinline__ void ldsm4(
    unsigned& r0, unsigned& r1, unsigned& r2, unsigned& r3, unsigned addr)
{
    asm volatile("ldmatrix.sync.aligned.m8n8.x4.shared.b16 {%0,%1,%2,%3}, [%4];"
        : "=r"(r0), "=r"(r1), "=r"(r2), "=r"(r3) : "r"(addr));
}

__device__ __forceinline__ void cp16(void* smem, const void* gmem) {
    unsigned sa = (unsigned)__cvta_generic_to_shared(smem);
    asm volatile("cp.async.cg.shared.global [%0], [%1], 16;" :: "r"(sa), "l"(gmem));
}
__device__ __forceinline__ void stcs2(float* p, float x, float y) {
    asm volatile("st.global.cs.v2.f32 [%0], {%1,%2};" :: "l"(p), "f"(x), "f"(y) : "memory");
}
#define CP_COMMIT() asm volatile("cp.async.commit_group;")
#define CP_WAIT0()  asm volatile("cp.async.wait_group 0;")
#define CP_WAIT1()  asm volatile("cp.async.wait_group 1;")
#define CP_WAIT2()  asm volatile("cp.async.wait_group 2;")

// ---------------------------------------------------------------------------
// fp32 -> fp16 conversion of all GEMM operands. 16M floats, float4/thread.
// ---------------------------------------------------------------------------
__global__ void __launch_bounds__(256) conv_half(
    const float* __restrict__ q, const float* __restrict__ k,
    const float* __restrict__ v,
    const float* __restrict__ wq, const float* __restrict__ wk,
    const float* __restrict__ wv, const float* __restrict__ wo)
{
    const size_t idx = (size_t)blockIdx.x * 256 + threadIdx.x;
    const size_t e = idx * 4;
    const float* src;
    __half* dst;
    size_t off;
    if (e < 4194304)        { src = q;  dst = h_qry; off = e; }
    else if (e < 8388608)   { src = k;  dst = h_key; off = e - 4194304; }
    else if (e < 12582912)  { src = v;  dst = h_val; off = e - 8388608; }
    else {
        const size_t e2 = e - 12582912;
        const int s = (int)(e2 >> 20);
        off = e2 & 1048575;
        src = (s == 0) ? wq : (s == 1) ? wk : (s == 2) ? wv : wo;
        dst = (s == 0) ? h_wq : (s == 1) ? h_wk : (s == 2) ? h_wv : h_wo;
    }
    const float4 f = *(const float4*)(src + off);
    *(__half2*)(dst + off)     = __float22half2_rn(make_float2(f.x, f.y));
    *(__half2*)(dst + off + 2) = __float22half2_rn(make_float2(f.z, f.w));
}

// ---------------------------------------------------------------------------
// fp16 GEMM core: block tile 64x128, 128 threads (4 warps, warp tile 64x32),
// K=1024, k-tile 64 halves, double-buffered cp.async, ldmatrix feeds.
// SINGLE barrier per k-iteration: wait(s) -> sync -> issue(s^1) -> compute(s).
// The barrier proves both "stage s landed for all warps" and "all warps
// finished reading s^1 in the previous iteration".
// ---------------------------------------------------------------------------
#define GEMM_SMEM ((2*64*72 + 2*128*72) * 2)   // 55296 B

struct GemmCoreH {
    float c[4][4][4];

    template<class SrcA>
    __device__ __forceinline__ void run(
        __half* smh, SrcA srcA, const __half* __restrict__ W,
        int M0, int N0, int tid, int wn, int lane)
    {
        __half* As = smh;                 // [2][64][72]
        __half* Ws = smh + 2 * 64 * 72;   // [2][128][72]
        const unsigned uAs = (unsigned)__cvta_generic_to_shared(As);
        const unsigned uWs = (unsigned)__cvta_generic_to_shared(Ws);
        const int quad = lane >> 3, r8 = lane & 7;
        const int aoff = (((quad & 1) << 3) + r8) * 72 + ((quad >> 1) << 3);
        const int boff = (((quad >> 1) << 3) + r8) * 72 + ((quad & 1) << 3);

        #pragma unroll
        for (int mi = 0; mi < 4; mi++)
            #pragma unroll
            for (int ni = 0; ni < 4; ni++)
                #pragma unroll
                for (int r = 0; r < 4; r++) c[mi][ni][r] = 0.f;

        auto issue = [&](int kt, int s) {
            const int k0 = kt * 64;
            #pragma unroll
            for (int p = 0; p < 4; p++) {
                const int cid = tid + p * 128;
                const int m = cid >> 3;
                const int cc = (cid & 7) << 3;
                cp16(&As[(size_t)(s * 64 + m) * 72 + cc], srcA(M0 + m, k0 + cc));
            }
            #pragma unroll
            for (int p = 0; p < 8; p++) {
                const int cid = tid + p * 128;
                const int m = cid >> 3;
                const int cc = (cid & 7) << 3;
                cp16(&Ws[(size_t)(s * 128 + m) * 72 + cc],
                     W + (size_t)(N0 + m) * 1024 + k0 + cc);
            }
            CP_COMMIT();
        };

        issue(0, 0);
        for (int kt = 0; kt < 16; kt++) {
            const int s = kt & 1;
            CP_WAIT0();
            __syncthreads();
            if (kt + 1 < 16) issue(kt + 1, s ^ 1);

            const unsigned aBase = uAs + (unsigned)((s * 64) * 72 + aoff) * 2;
            const unsigned bBase = uWs + (unsigned)((s * 128 + wn * 32) * 72 + boff) * 2;
            #pragma unroll
            for (int ks = 0; ks < 4; ks++) {
                const int kk = ks * 16;
                unsigned af[4][4], bf[4][2];
                #pragma unroll
                for (int mi = 0; mi < 4; mi++)
                    ldsm4(af[mi][0], af[mi][1], af[mi][2], af[mi][3],
                          aBase + (unsigned)(mi * 16 * 72 + kk) * 2);
                #pragma unroll
                for (int np = 0; np < 2; np++)
                    ldsm4(bf[2*np][0], bf[2*np][1], bf[2*np+1][0], bf[2*np+1][1],
                          bBase + (unsigned)(np * 16 * 72 + kk) * 2);
                #pragma unroll
                for (int mi = 0; mi < 4; mi++)
                    #pragma unroll
                    for (int ni = 0; ni < 4; ni++)
                        mma_f16(c[mi][ni][0], c[mi][ni][1], c[mi][ni][2], c[mi][ni][3],
                                af[mi][0], af[mi][1], af[mi][2], af[mi][3],
                                bf[ni][0], bf[ni][1]);
            }
        }
    }
};

// ---------------------------------------------------------------------------
// Merged Q/K/V projection: 1536 blocks of 128 threads, z = g>>9.
// ---------------------------------------------------------------------------
__global__ void __launch_bounds__(128, 4) qkv_gemm(
    const float* __restrict__ Wq_b, const float* __restrict__ Wk_b,
    const float* __restrict__ Wv_b)
{
    extern __shared__ __half smh[];
    const int g = blockIdx.x;
    const int z = g >> 9;
    const int r = g & 511;
    const int tid = threadIdx.x;
    const int lane = tid & 31;
    const int grp = lane >> 2;
    const int tig = lane & 3;
    const int wn = tid >> 5;

    const __half *A, *W;
    const float* bias;
    int M0, N0;
    if (z == 0)      { A = h_qry; W = h_wq; bias = Wq_b; M0 = (r >> 3) * 64; N0 = (r & 7) * 128; }
    else if (z == 1) { A = h_key; W = h_wk; bias = Wk_b; M0 = (r >> 3) * 64; N0 = (r & 7) * 128; }
    else             { A = h_wv;  W = h_val; bias = Wv_b; M0 = (r & 15) * 64; N0 = (r >> 4) * 128; }

    GemmCoreH gc;
    gc.run(smh, [&](int m, int k) { return (const void*)(A + (size_t)m * 1024 + k); },
           W, M0, N0, tid, wn, lane);

    #pragma unroll
    for (int mi = 0; mi < 4; mi++) {
        #pragma unroll
        for (int ni = 0; ni < 4; ni++) {
            const int r0 = M0 + mi * 16 + grp;
            const int r1 = r0 + 8;
            const int cn = N0 + wn * 32 + ni * 8 + tig * 2;
            if (z == 2) {
                const float bv0 = bias[r0], bv1 = bias[r1];
                const size_t base = (size_t)(cn >> 10) * 1048576 + (cn & 1023);
                *(__half2*)(g_vh + base + (size_t)r0 * 1024) =
                    __float22half2_rn(make_float2(gc.c[mi][ni][0] + bv0, gc.c[mi][ni][1] + bv0));
                *(__half2*)(g_vh + base + (size_t)r1 * 1024) =
                    __float22half2_rn(make_float2(gc.c[mi][ni][2] + bv1, gc.c[mi][ni][3] + bv1));
            } else {
                __half* dst = (z == 0) ? g_qh : g_kh;
                const float bv0 = bias[cn], bv1 = bias[cn + 1];
                const int h = cn >> 6, d = cn & 63;
                const int bi0 = r0 >> 10, l0 = r0 & 1023;
                const int bi1 = r1 >> 10, l1 = r1 & 1023;
                *(__half2*)(dst + (((size_t)(bi0 * Hdim + h)) * Ldim + l0) * Ddim + d) =
                    __float22half2_rn(make_float2(gc.c[mi][ni][0] + bv0, gc.c[mi][ni][1] + bv1));
                *(__half2*)(dst + (((size_t)(bi1 * Hdim + h)) * Ldim + l1) * Ddim + d) =
                    __float22half2_rn(make_float2(gc.c[mi][ni][2] + bv0, gc.c[mi][ni][3] + bv1));
            }
        }
    }
}

// ---------------------------------------------------------------------------
// Output projection: out = merge_heads(g_atth) @ Wo^T + bo (fp32 out)
// ---------------------------------------------------------------------------
__global__ void __launch_bounds__(128, 4) out_gemm(
    const float* __restrict__ bias,
    float* __restrict__ Cout)
{
    extern __shared__ __half smh[];
    const int M0 = blockIdx.y * 64;
    const int N0 = blockIdx.x * 128;
    const int tid = threadIdx.x;
    const int lane = tid & 31;
    const int grp = lane >> 2;
    const int tig = lane & 3;
    const int wn = tid >> 5;

    GemmCoreH gc;
    gc.run(smh,
        [&](int m, int k) {
            const int bi = m >> 10, l = m & 1023;
            const int h = k >> 6, d = k & 63;
            return (const void*)(g_atth + (((size_t)(bi * Hdim + h)) * Ldim + l) * Ddim + d);
        },
        h_wo, M0, N0, tid, wn, lane);

    #pragma unroll
    for (int mi = 0; mi < 4; mi++) {
        #pragma unroll
        for (int ni = 0; ni < 4; ni++) {
            const int r0 = M0 + mi * 16 + grp;
            const int r1 = r0 + 8;
            const int cn = N0 + wn * 32 + ni * 8 + tig * 2;
            const float bv0 = bias[cn], bv1 = bias[cn + 1];
            *(float2*)(Cout + (size_t)r0 * 1024 + cn) =
                make_float2(gc.c[mi][ni][0] + bv0, gc.c[mi][ni][1] + bv1);
            *(float2*)(Cout + (size_t)r1 * 1024 + cn) =
                make_float2(gc.c[mi][ni][2] + bv0, gc.c[mi][ni][3] + bv1);
        }
    }
}

// ---------------------------------------------------------------------------
// Fused flash attention: 64-query blocks, 128 threads (4 warps x 16 rows).
// K and V double-buffered; prev/P buffer is WARP-LOCAL (each warp cp-fills,
// reads, exp-overwrites, and ldsm-reads only its own 16 rows) so it needs no
// block barrier. Only 2 __syncthreads per key-tile:
//   sync#1: K[t] visible + all reads of previous tile's buffers finished.
//   sync#2: V[t] visible block-wide.
// cp.async groups per tile, FIFO order: K, V, P.
// ---------------------------------------------------------------------------
#define SMEM_FUSED ((64*72 * 5) * 2 + 64*68*4)   // 63488 B

__global__ void __launch_bounds__(128, 3) fused_attn(
    const float* __restrict__ prev,
    const int* __restrict__ mask,
    const float* __restrict__ gat,
    float* __restrict__ scores)
{
    extern __shared__ __half smh[];
    __half* uQh = smh;                      // [64][72]
    __half* fKh = uQh + 64 * 72;            // [2][64][72] K tiles [j][d]
    __half* fVh = fKh + 2 * 64 * 72;        // [2][64][72] V^T tiles [d][j]
    float*  fP  = (float*)(fVh + 2 * 64 * 72);  // [64][68] prev fp32 / P half2
    unsigned* uP = (unsigned*)fP;

    const unsigned uQb = (unsigned)__cvta_generic_to_shared(uQh);
    const unsigned uKb = (unsigned)__cvta_generic_to_shared(fKh);
    const unsigned uVb = (unsigned)__cvta_generic_to_shared(fVh);
    const unsigned uPb = (unsigned)__cvta_generic_to_shared(fP);

    const int bh = blockIdx.y;
    const int q0 = blockIdx.x * 64;
    const int tid = threadIdx.x;
    const int w = tid >> 5;
    const int lane = tid & 31;
    const int grp = lane >> 2;
    const int tig = lane & 3;
    const int quad = lane >> 3, r8 = lane & 7;
    const int aoff72  = (((quad & 1) << 3) + r8) * 72 + ((quad >> 1) << 3);
    const int aoff136 = (((quad & 1) << 3) + r8) * 136 + ((quad >> 1) << 3);
    const int boff72  = (((quad >> 1) << 3) + r8) * 72 + ((quad & 1) << 3);
    const int rw0 = w * 16 + grp;
    const int rw1 = rw0 + 8;
    const int gq0 = q0 + rw0;
    const int gq1 = q0 + rw1;

    const __half* qgh = g_qh + (size_t)bh * Ldim * Ddim;
    const __half* kgh = g_kh + (size_t)bh * Ldim * Ddim;
    const __half* vgh = g_vh + (size_t)bh * Ddim * Ldim;  // [d][l]
    const size_t sb = ((size_t)bh << 20);
    const float* prevb = prev + sb + (size_t)(q0 + w * 16) * Ldim;

    auto issueK = [&](int kt, int s) {
        __half* dst = fKh + s * 64 * 72;
        #pragma unroll
        for (int p = 0; p < 4; p++) {
            const int cid = tid + p * 128;
            const int r = cid >> 3;
            const int cc = (cid & 7) << 3;
            cp16(&dst[r * 72 + cc], kgh + (size_t)(kt + r) * Ddim + cc);
        }
        CP_COMMIT();
    };
    auto issueV = [&](int kt, int s) {
        __half* dst = fVh + s * 64 * 72;
        #pragma unroll
        for (int p = 0; p < 4; p++) {
            const int cid = tid + p * 128;
            const int r = cid >> 3;
            const int cc = (cid & 7) << 3;
            cp16(&dst[r * 72 + cc], vgh + (size_t)r * Ldim + kt + cc);
        }
        CP_COMMIT();
    };
    auto issueP = [&](int kt) {
        #pragma unroll
        for (int j = 0; j < 8; j++) {
            const int cid = j * 32 + lane;
            const int r = cid >> 4;
            const int c4 = (cid & 15) << 2;
            cp16(&fP[(w * 16 + r) * 68 + c4], prevb + (size_t)r * Ldim + kt + c4);
        }
        CP_COMMIT();
    };

    issueK(0, 0);
    issueV(0, 0);
    issueP(0);

    // Q tile once: 64 x 64 halves
    #pragma unroll
    for (int p = 0; p < 4; p++) {
        const int cid = tid + p * 128;
        const int m = cid >> 3;
        const int cc = (cid & 7) << 3;
        *(uint4*)&uQh[m * 72 + cc] = *(const uint4*)(qgh + (size_t)(q0 + m) * Ddim + cc);
    }

    const int vl0 = mask[(bh & 3) * Ldim + gq0];
    const int vl1 = mask[(bh & 3) * Ldim + gq1];
    const float gv = 1.f / (1.f + __expf(-gat[0]));
    const float og = 1.f - gv;

    float o[8][4];
    #pragma unroll
    for (int ni = 0; ni < 8; ni++)
        #pragma unroll
        for (int r = 0; r < 4; r++) o[ni][r] = 0.f;
    float mi0 = -1e30f, mi1 = -1e30f, li0 = 0.f, li1 = 0.f;

    for (int ti = 0; ti < 16; ti++) {
        const int kt = ti * 64;
        const int s = ti & 1;
        const bool more = (ti + 1 < 16);

        // pending: {K[t], V[t], P[t]} -> retire K
        CP_WAIT2();
        __syncthreads();               // K visible; prev-tile buffer reads done
        if (more) issueK(kt + 64, s ^ 1);

        // S = Q @ K^T  (stage s)
        float cs[8][4];
        #pragma unroll
        for (int ni = 0; ni < 8; ni++)
            #pragma unroll
            for (int r = 0; r < 4; r++) cs[ni][r] = 0.f;

        const unsigned kBase = uKb + (unsigned)(s * 64 * 72) * 2;
        #pragma unroll
        for (int ks = 0; ks < 4; ks++) {
            const int kk = ks * 16;
            unsigned a0, a1, a2, a3;
            ldsm4(a0, a1, a2, a3, uQb + (unsigned)(w * 16 * 72 + kk + aoff72) * 2);
            unsigned bf[8][2];
            #pragma unroll
            for (int np = 0; np < 4; np++)
                ldsm4(bf[2*np][0], bf[2*np][1], bf[2*np+1][0], bf[2*np+1][1],
                      kBase + (unsigned)(np * 16 * 72 + kk + boff72) * 2);
            #pragma unroll
            for (int ni = 0; ni < 8; ni++)
                mma_f16(cs[ni][0], cs[ni][1], cs[ni][2], cs[ni][3],
                        a0, a1, a2, a3, bf[ni][0], bf[ni][1]);
        }

        // pending: {V[t], P[t], (K[t+1])} -> retire V
        if (more) CP_WAIT2(); else CP_WAIT1();
        __syncthreads();               // V visible block-wide
        if (more) issueV(kt + 64, s ^ 1);

        // pending: {P[t], (K[t+1], V[t+1])} -> retire P (own-warp data)
        if (more) CP_WAIT2(); else CP_WAIT0();

        // blend with prev, write scores (streaming), mask+scale
        float m0 = -1e30f, m1 = -1e30f;
        #pragma unroll
        for (int ni = 0; ni < 8; ni++) {
            const int cl = ni * 8 + tig * 2;
            const int col = kt + cl;
            const float2 p0 = *(const float2*)&fP[rw0 * 68 + cl];
            const float2 p1 = *(const float2*)&fP[rw1 * 68 + cl];
            const float b00 = p0.x * gv + og * cs[ni][0];
            const float b01 = p0.y * gv + og * cs[ni][1];
            const float b10 = p1.x * gv + og * cs[ni][2];
            const float b11 = p1.y * gv + og * cs[ni][3];
            stcs2(scores + sb + (size_t)gq0 * Ldim + col, b00, b01);
            stcs2(scores + sb + (size_t)gq1 * Ldim + col, b10, b11);
            cs[ni][0] = (col     < vl0) ? b00 * 0.125f : -1e30f;
            cs[ni][1] = (col + 1 < vl0) ? b01 * 0.125f : -1e30f;
            cs[ni][2] = (col     < vl1) ? b10 * 0.125f : -1e30f;
            cs[ni][3] = (col + 1 < vl1) ? b11 * 0.125f : -1e30f;
            m0 = fmaxf(m0, fmaxf(cs[ni][0], cs[ni][1]));
            m1 = fmaxf(m1, fmaxf(cs[ni][2], cs[ni][3]));
        }
        m0 = fmaxf(m0, __shfl_xor_sync(0xffffffffu, m0, 1));
        m0 = fmaxf(m0, __shfl_xor_sync(0xffffffffu, m0, 2));
        m1 = fmaxf(m1, __shfl_xor_sync(0xffffffffu, m1, 1));
        m1 = fmaxf(m1, __shfl_xor_sync(0xffffffffu, m1, 2));

        const float mn0 = fmaxf(mi0, m0);
        const float mn1 = fmaxf(mi1, m1);
        const float cr0 = __expf(mi0 - mn0);
        const float cr1 = __expf(mi1 - mn1);
        li0 *= cr0; li1 *= cr1;
        #pragma unroll
        for (int ni = 0; ni < 8; ni++) {
            o[ni][0] *= cr0; o[ni][1] *= cr0;
            o[ni][2] *= cr1; o[ni][3] *= cr1;
        }
        mi0 = mn0; mi1 = mn1;

        // P = exp(s - m) -> half2 into uP (warp-local rows)
        #pragma unroll
        for (int ni = 0; ni < 8; ni++) {
            const float p00 = __expf(cs[ni][0] - mn0);
            const float p01 = __expf(cs[ni][1] - mn0);
            const float p10 = __expf(cs[ni][2] - mn1);
            const float p11 = __expf(cs[ni][3] - mn1);
            li0 += p00 + p01;
            li1 += p10 + p11;
            const int pc = ni * 4 + tig;
            uP[rw0 * 68 + pc] = f2h2(p00, p01);
            uP[rw1 * 68 + pc] = f2h2(p10, p11);
        }
        __syncwarp();

        // O += P @ V (P rows warp-local; V stage s block-visible via sync#2)
        const unsigned vBase = uVb + (unsigned)(s * 64 * 72) * 2;
        #pragma unroll
        for (int ks = 0; ks < 4; ks++) {
            const int kk = ks * 16;
            unsigned a0, a1, a2, a3;
            ldsm4(a0, a1, a2, a3, uPb + (unsigned)(w * 16 * 136 + kk + aoff136) * 2);
            unsigned bf[8][2];
            #pragma unroll
            for (int np = 0; np < 4; np++)
                ldsm4(bf[2*np][0], bf[2*np][1], bf[2*np+1][0], bf[2*np+1][1],
                      vBase + (unsigned)(np * 16 * 72 + kk + boff72) * 2);
            #pragma unroll
            for (int ni = 0; ni < 8; ni++)
                mma_f16(o[ni][0], o[ni][1], o[ni][2], o[ni][3],
                        a0, a1, a2, a3, bf[ni][0], bf[ni][1]);
        }

        // P buffer fully consumed by this warp -> refill for next tile, no bar
        if (more) issueP(kt + 64);
    }

    li0 += __shfl_xor_sync(0xffffffffu, li0, 1);
    li0 += __shfl_xor_sync(0xffffffffu, li0, 2);
    li1 += __shfl_xor_sync(0xffffffffu, li1, 1);
    li1 += __shfl_xor_sync(0xffffffffu, li1, 2);
    const float inv0 = 1.f / li0;
    const float inv1 = 1.f / li1;

    __half* ab = g_atth + (size_t)bh * Ldim * Ddim;
    #pragma unroll
    for (int ni = 0; ni < 8; ni++) {
        const int d = ni * 8 + tig * 2;
        *(__half2*)(ab + (size_t)gq0 * Ddim + d) =
            __float22half2_rn(make_float2(o[ni][0] * inv0, o[ni][1] * inv0));
        *(__half2*)(ab + (size_t)gq1 * Ddim + d) =
            __float22half2_rn(make_float2(o[ni][2] * inv1, o[ni][3] * inv1));
    }
}

// ---------------------------------------------------------------------------
// Launch.  Inputs: queries, keys, values, prev, mask(int32),
//   Wq_w, Wq_b, Wk_w, Wk_b, Wv_w, Wv_b, Wo_w, Wo_b, gat
// Output: [out (4M floats) | scores (64M floats)]
// ---------------------------------------------------------------------------
extern "C" void kernel_launch(void* const* d_in, const int* in_sizes, int n_in,
                              void* d_out, int out_size)
{
    (void)in_sizes; (void)n_in; (void)out_size;
    const float* queries = (const float*)d_in[0];
    const float* keys    = (const float*)d_in[1];
    const float* values  = (const float*)d_in[2];
    const float* prev    = (const float*)d_in[3];
    const int*   mask    = (const int*)d_in[4];
    const float* Wq_w = (const float*)d_in[5];
    const float* Wq_b = (const float*)d_in[6];
    const float* Wk_w = (const float*)d_in[7];
    const float* Wk_b = (const float*)d_in[8];
    const float* Wv_w = (const float*)d_in[9];
    const float* Wv_b = (const float*)d_in[10];
    const float* Wo_w = (const float*)d_in[11];
    const float* Wo_b = (const float*)d_in[12];
    const float* gat  = (const float*)d_in[13];

    float* out    = (float*)d_out;
    float* scores = out + (size_t)Bdim * Ldim * HIDdim;

    cudaFuncSetAttribute(fused_attn,
                         cudaFuncAttributeMaxDynamicSharedMemorySize, SMEM_FUSED);
    cudaFuncSetAttribute(qkv_gemm,
                         cudaFuncAttributeMaxDynamicSharedMemorySize, GEMM_SMEM);
    cudaFuncSetAttribute(out_gemm,
                         cudaFuncAttributeMaxDynamicSharedMemorySize, GEMM_SMEM);

    conv_half<<<16384, 256>>>(queries, keys, values, Wq_w, Wk_w, Wv_w, Wo_w);

    qkv_gemm<<<1536, 128, GEMM_SMEM>>>(Wq_b, Wk_b, Wv_b);

    dim3 gf(16, 64);
    fused_attn<<<gf, 128, SMEM_FUSED>>>(prev, mask, gat, scores);

    dim3 gproj(8, 64);
    out_gemm<<<gproj, 128, GEMM_SMEM>>>(Wo_b, out);
}